// round 2
// baseline (speedup 1.0000x reference)
#include <cuda_runtime.h>
#include <math.h>

// Problem constants (fixed shapes)
#define B_  2
#define S_  1024
#define D_  1024
#define H_  16
#define DH_ 64
#define NB_ 256
#define NC_ 257     // compressed keys = mem + 256 blocks
#define FD_ 4096
#define ROWS_ (B_*S_)   // 2048

// ---------------- scratch (static device arrays; no allocation) ----------------
__device__ float g_xr[B_*S_*D_];
__device__ float g_h [B_*S_*D_];
__device__ float g_q [B_*S_*D_];
__device__ float g_k [B_*S_*D_];
__device__ float g_v [B_*S_*D_];
__device__ float g_qr[B_*S_*D_];
__device__ float g_kr[B_*S_*D_];
__device__ float g_kc[B_*NC_*H_*DH_];
__device__ float g_vc[B_*NC_*H_*DH_];
__device__ float g_gate[B_*S_*48];
__device__ float g_o [B_*S_*D_];
__device__ float g_x1[B_*S_*D_];
__device__ float g_m [B_*S_*D_];
__device__ float g_act[B_*S_*FD_];

// ---------------- K1: xr = l0*x + l1*x0 ; h = rmsnorm(xr) ----------------
__global__ void k_rms1(const float* __restrict__ x, const float* __restrict__ x0,
                       const float* __restrict__ lam) {
    const int row = blockIdx.x;
    const int t = threadIdx.x;
    const float l0 = lam[0], l1 = lam[1];
    const size_t base = (size_t)row * D_;
    __shared__ float red[8];
    __shared__ float s_inv;
    float ss = 0.f;
    for (int i = t; i < D_; i += 256) {
        float v = l0 * x[base + i] + l1 * x0[base + i];
        g_xr[base + i] = v;
        ss += v * v;
    }
#pragma unroll
    for (int o = 16; o; o >>= 1) ss += __shfl_xor_sync(0xffffffffu, ss, o);
    if ((t & 31) == 0) red[t >> 5] = ss;
    __syncthreads();
    if (t == 0) {
        float tot = 0.f;
        for (int w = 0; w < 8; w++) tot += red[w];
        s_inv = rsqrtf(tot / (float)D_ + 1e-6f);
    }
    __syncthreads();
    const float inv = s_inv;
    for (int i = t; i < D_; i += 256) g_h[base + i] = g_xr[base + i] * inv;
}

// ---------------- rmsnorm(x1) -> m ----------------
__global__ void k_rms2() {
    const int row = blockIdx.x;
    const int t = threadIdx.x;
    const size_t base = (size_t)row * D_;
    __shared__ float red[8];
    __shared__ float s_inv;
    float ss = 0.f;
    for (int i = t; i < D_; i += 256) { float v = g_x1[base + i]; ss += v * v; }
#pragma unroll
    for (int o = 16; o; o >>= 1) ss += __shfl_xor_sync(0xffffffffu, ss, o);
    if ((t & 31) == 0) red[t >> 5] = ss;
    __syncthreads();
    if (t == 0) {
        float tot = 0.f;
        for (int w = 0; w < 8; w++) tot += red[w];
        s_inv = rsqrtf(tot / (float)D_ + 1e-6f);
    }
    __syncthreads();
    const float inv = s_inv;
    for (int i = t; i < D_; i += 256) g_m[base + i] = g_x1[base + i] * inv;
}

// ---------------- SGEMM: C[M,N] = A[M,K] @ B[K,N] (+epilogue) ----------------
// 128x128 tile, BK=8, 256 threads, 8x8 per thread. M,N multiples of 128, K of 8.
// EPI: 0 = store, 1 = store C=AB+Add, 2 = store relu(AB)^2
template <int EPI>
__device__ __forceinline__ void sgemm_body(const float* __restrict__ A,
                                           const float* __restrict__ B,
                                           float* __restrict__ C,
                                           const float* __restrict__ Add,
                                           int M, int N, int K) {
    __shared__ float As[8][128];
    __shared__ float Bs[8][128];
    const int tid = threadIdx.x;
    const int bx = blockIdx.x, by = blockIdx.y;
    const int aRow = tid >> 1;
    const int aCol = (tid & 1) << 2;
    const int bRow = tid >> 5;
    const int bCol = (tid & 31) << 2;
    const int tr = (tid >> 4) << 3;
    const int tc = (tid & 15) << 3;
    float acc[8][8];
#pragma unroll
    for (int i = 0; i < 8; i++)
#pragma unroll
        for (int j = 0; j < 8; j++) acc[i][j] = 0.f;

    const float* Ap = A + (size_t)(by * 128 + aRow) * K + aCol;
    const float* Bp = B + (size_t)bRow * N + bx * 128 + bCol;

    for (int k0 = 0; k0 < K; k0 += 8) {
        float4 a4 = *(const float4*)(Ap + k0);
        As[aCol + 0][aRow] = a4.x;
        As[aCol + 1][aRow] = a4.y;
        As[aCol + 2][aRow] = a4.z;
        As[aCol + 3][aRow] = a4.w;
        float4 b4 = *(const float4*)(Bp + (size_t)k0 * N);
        *(float4*)&Bs[bRow][bCol] = b4;
        __syncthreads();
#pragma unroll
        for (int kk = 0; kk < 8; kk++) {
            float ar[8], br[8];
#pragma unroll
            for (int i = 0; i < 8; i++) ar[i] = As[kk][tr + i];
#pragma unroll
            for (int j = 0; j < 8; j++) br[j] = Bs[kk][tc + j];
#pragma unroll
            for (int i = 0; i < 8; i++)
#pragma unroll
                for (int j = 0; j < 8; j++) acc[i][j] += ar[i] * br[j];
        }
        __syncthreads();
    }
#pragma unroll
    for (int i = 0; i < 8; i++) {
        const int row = by * 128 + tr + i;
#pragma unroll
        for (int j = 0; j < 8; j += 4) {
            size_t idx = (size_t)row * N + bx * 128 + tc + j;
            float4 v;
            v.x = acc[i][j + 0]; v.y = acc[i][j + 1];
            v.z = acc[i][j + 2]; v.w = acc[i][j + 3];
            if (EPI == 1) {
                float4 ad = *(const float4*)(Add + idx);
                v.x += ad.x; v.y += ad.y; v.z += ad.z; v.w += ad.w;
            } else if (EPI == 2) {
                v.x = fmaxf(v.x, 0.f); v.x *= v.x;
                v.y = fmaxf(v.y, 0.f); v.y *= v.y;
                v.z = fmaxf(v.z, 0.f); v.z *= v.z;
                v.w = fmaxf(v.w, 0.f); v.w *= v.w;
            }
            *(float4*)(C + idx) = v;
        }
    }
}

__global__ void __launch_bounds__(256) gemm_q(const float* __restrict__ W) {
    sgemm_body<0>(g_h, W, g_q, nullptr, ROWS_, D_, D_);
}
__global__ void __launch_bounds__(256) gemm_k(const float* __restrict__ W) {
    sgemm_body<0>(g_h, W, g_k, nullptr, ROWS_, D_, D_);
}
__global__ void __launch_bounds__(256) gemm_v(const float* __restrict__ W) {
    sgemm_body<0>(g_h, W, g_v, nullptr, ROWS_, D_, D_);
}
__global__ void __launch_bounds__(256) gemm_o(const float* __restrict__ W) {
    sgemm_body<1>(g_o, W, g_x1, g_xr, ROWS_, D_, D_);
}
__global__ void __launch_bounds__(256) gemm_fc(const float* __restrict__ W) {
    sgemm_body<2>(g_m, W, g_act, nullptr, ROWS_, FD_, D_);
}
__global__ void __launch_bounds__(256) gemm_proj(const float* __restrict__ W, float* __restrict__ out) {
    sgemm_body<1>(g_act, W, out, g_x1, ROWS_, D_, FD_);
}

// ---------------- gates: g = sigmoid(h @ Wg), Wg (D,48) ----------------
__global__ void k_gate(const float* __restrict__ Wg) {
    const int row = blockIdx.x;
    const int t = threadIdx.x;   // 64 threads
    __shared__ float hrow[D_];
    for (int i = t; i < D_; i += 64) hrow[i] = g_h[(size_t)row * D_ + i];
    __syncthreads();
    if (t < 48) {
        float a = 0.f;
        for (int kk = 0; kk < D_; kk++) a += hrow[kk] * Wg[kk * 48 + t];
        g_gate[(size_t)row * 48 + t] = 1.f / (1.f + expf(-a));
    }
}

// ---------------- block compression: kc/vc for n>=1 ----------------
__global__ void k_compress(const float* __restrict__ pos_k, const float* __restrict__ pos_v,
                           const float* __restrict__ Wck, const float* __restrict__ Wcv) {
    const int idx = blockIdx.x;   // B*NB*H = 8192
    const int h = idx & (H_ - 1);
    const int n = (idx >> 4) & (NB_ - 1);
    const int b = idx >> 12;
    const int t = threadIdx.x;    // 64
    __shared__ float kb[256], vb[256];
    for (int r = t; r < 256; r += 64) {
        const int sp = r >> 6, d = r & 63;
        const int s = n * 4 + sp;
        const size_t src = ((size_t)(b * S_ + s) * H_ + h) * DH_ + d;
        kb[r] = g_k[src] + pos_k[(h * 4 + sp) * DH_ + d];
        vb[r] = g_v[src] + pos_v[(h * 4 + sp) * DH_ + d];
    }
    __syncthreads();
    float ak = 0.f, av = 0.f;
    for (int r = 0; r < 256; r++) {
        ak += kb[r] * Wck[r * DH_ + t];
        av += vb[r] * Wcv[r * DH_ + t];
    }
    const size_t dst = ((size_t)(b * NC_ + (n + 1)) * H_ + h) * DH_ + t;
    g_kc[dst] = ak;
    g_vc[dst] = av;
}

__global__ void k_memfill(const float* __restrict__ mem_k, const float* __restrict__ mem_v) {
    const int i = blockIdx.x * blockDim.x + threadIdx.x;  // B*H*DH = 2048
    if (i >= B_ * H_ * DH_) return;
    const int d = i & 63, h = (i >> 6) & (H_ - 1), b = i >> 10;
    const size_t dst = ((size_t)(b * NC_ + 0) * H_ + h) * DH_ + d;
    g_kc[dst] = mem_k[h * DH_ + d];
    g_vc[dst] = mem_v[h * DH_ + d];
}

// ---------------- RoPE: qr = rope(q), kr = rope(k) ----------------
__global__ void k_rope() {
    const int i = blockIdx.x * blockDim.x + threadIdx.x;  // B*S*H*32
    if (i >= B_ * S_ * H_ * 32) return;
    const int p = i & 31;
    const int h = (i >> 5) & (H_ - 1);
    const int s = (i >> 9) & (S_ - 1);
    const int b = i >> 19;
    const float inv = powf(10000.f, -(float)p / 32.f);
    const float tt = (float)s * inv;
    const float c = cosf(tt), sn = sinf(tt);
    const size_t base = ((size_t)(b * S_ + s) * H_ + h) * DH_;
    float q1 = g_q[base + p], q2 = g_q[base + 32 + p];
    g_qr[base + p]      = q1 * c - q2 * sn;
    g_qr[base + 32 + p] = q1 * sn + q2 * c;
    float k1 = g_k[base + p], k2 = g_k[base + 32 + p];
    g_kr[base + p]      = k1 * c - k2 * sn;
    g_kr[base + 32 + p] = k1 * sn + k2 * c;
}

// ---------------- mega attention: compressed + top4 + fine + sliding + gate ----------------
__global__ void __launch_bounds__(256) k_attn() {
    const int idx = blockIdx.x;           // B*H*S = 32768
    const int s = idx & (S_ - 1);
    const int h = (idx >> 10) & (H_ - 1);
    const int b = idx >> 14;
    const int t = threadIdx.x;

    __shared__ float qv[64], qrv[64];
    __shared__ float sc[NC_];
    __shared__ float red[8];
    __shared__ float fsc[20];
    __shared__ int   fkp[20];
    __shared__ float ssc[32];
    __shared__ float outc[64], outf[64], outs[64];
    __shared__ int   sel[4];
    __shared__ int   s_nv;
    __shared__ float s_bmax, s_bsum, s_fsum, s_ssum;

    const size_t qbase = ((size_t)(b * S_ + s) * H_ + h) * DH_;
    if (t < 64) { qv[t] = g_q[qbase + t]; qrv[t] = g_qr[qbase + t]; }
    __syncthreads();

    // ---- compressed attention over nk keys ----
    const int nvisB = (s >= 3) ? (((s - 3) >> 2) + 1) : 0;   // visible 4-blocks
    const int nk = nvisB + 1;                                 // + mem slot (n=0)

    for (int n = t; n < nk; n += 256) {
        const float* kcp = g_kc + ((size_t)(b * NC_ + n) * H_ + h) * DH_;
        float a = 0.f;
#pragma unroll
        for (int d = 0; d < 64; d++) a += qv[d] * kcp[d];
        sc[n] = a * 0.125f;
    }
    __syncthreads();

    // max
    float mx = -1e30f;
    for (int n = t; n < nk; n += 256) mx = fmaxf(mx, sc[n]);
#pragma unroll
    for (int o = 16; o; o >>= 1) mx = fmaxf(mx, __shfl_xor_sync(0xffffffffu, mx, o));
    if ((t & 31) == 0) red[t >> 5] = mx;
    __syncthreads();
    if (t == 0) {
        float m2 = red[0];
        for (int w = 1; w < 8; w++) m2 = fmaxf(m2, red[w]);
        s_bmax = m2;
    }
    __syncthreads();
    // exp + sum
    float sm = 0.f;
    const float bmax = s_bmax;
    for (int n = t; n < nk; n += 256) { float e = expf(sc[n] - bmax); sc[n] = e; sm += e; }
#pragma unroll
    for (int o = 16; o; o >>= 1) sm += __shfl_xor_sync(0xffffffffu, sm, o);
    if ((t & 31) == 0) red[t >> 5] = sm;
    __syncthreads();
    if (t == 0) {
        float tot = 0.f;
        for (int w = 0; w < 8; w++) tot += red[w];
        s_bsum = tot;
        // ---- top-4 over blocks (n in [1, nk)) ; ties -> lower index (strict >) ----
        float tv[4] = {-1.f, -1.f, -1.f, -1.f};
        int   ti[4] = {0, 0, 0, 0};
        for (int n = 1; n < nk; n++) {
            float vI = sc[n];
            if (vI > tv[3]) {
                int p2 = 3;
                while (p2 > 0 && vI > tv[p2 - 1]) {
                    tv[p2] = tv[p2 - 1]; ti[p2] = ti[p2 - 1]; p2--;
                }
                tv[p2] = vI; ti[p2] = n - 1;
            }
        }
        int nv = nvisB < 4 ? nvisB : 4;
        s_nv = nv;
        sel[0] = ti[0]; sel[1] = ti[1]; sel[2] = ti[2]; sel[3] = ti[3];
        for (int m = nv; m < 4; m++) sel[m] = 0;
    }
    __syncthreads();

    // ---- cout (threads 0..63) + fine scores (64..83) + sliding scores (96..127) ----
    if (t < 64) {
        float a = 0.f;
        const float* vcp = g_vc + ((size_t)(b * NC_) * H_ + h) * DH_ + t;
        for (int n = 0; n < nk; n++) a += sc[n] * vcp[(size_t)n * H_ * DH_];
        outc[t] = a / s_bsum;
    } else if (t < 84) {
        const int j = t - 64;               // key index within 20
        const int m = j >> 2, sp = j & 3;
        const int blk = (m == 4) ? (s >> 2) : sel[m];
        const int kp = blk * 4 + sp;
        bool vis = ((m == 4) || (m < s_nv)) && (kp <= s);
        float a = -1e30f;
        if (vis) {
            const float* kpp = g_kr + ((size_t)(b * S_ + kp) * H_ + h) * DH_;
            a = 0.f;
#pragma unroll
            for (int d = 0; d < 64; d++) a += qrv[d] * kpp[d];
            a *= 0.125f;
        }
        fsc[j] = a;
        fkp[j] = kp;
    } else if (t >= 96 && t < 128) {
        const int w = t - 96;
        const int pos = s - w;
        float a = -1e30f;
        if (pos >= 0) {
            const float* kpp = g_kr + ((size_t)(b * S_ + pos) * H_ + h) * DH_;
            a = 0.f;
#pragma unroll
            for (int d = 0; d < 64; d++) a += qrv[d] * kpp[d];
            a *= 0.125f;
        }
        ssc[w] = a;
    }
    __syncthreads();

    // small softmaxes
    if (t == 0) {
        float mxf = -1e30f;
        for (int j = 0; j < 20; j++) mxf = fmaxf(mxf, fsc[j]);
        float sm2 = 0.f;
        for (int j = 0; j < 20; j++) {
            float e = (fsc[j] > -1e29f) ? expf(fsc[j] - mxf) : 0.f;
            fsc[j] = e; sm2 += e;
        }
        s_fsum = sm2;
    } else if (t == 32) {
        float mxs = -1e30f;
        for (int w = 0; w < 32; w++) mxs = fmaxf(mxs, ssc[w]);
        float sm3 = 0.f;
        for (int w = 0; w < 32; w++) {
            float e = (ssc[w] > -1e29f) ? expf(ssc[w] - mxs) : 0.f;
            ssc[w] = e; sm3 += e;
        }
        s_ssum = sm3;
    }
    __syncthreads();

    // weighted sums
    if (t < 64) {
        float a = 0.f;
        for (int j = 0; j < 20; j++)
            a += fsc[j] * g_v[((size_t)(b * S_ + fkp[j]) * H_ + h) * DH_ + t];
        outf[t] = a / s_fsum;
    } else if (t < 128) {
        const int d = t - 64;
        float a = 0.f;
        const int wmax = s < 31 ? s : 31;
        for (int w = 0; w <= wmax; w++)
            a += ssc[w] * g_v[((size_t)(b * S_ + (s - w)) * H_ + h) * DH_ + d];
        outs[d] = a / s_ssum;
    }
    __syncthreads();

    if (t < 64) {
        const float* gg = g_gate + (size_t)(b * S_ + s) * 48 + h * 3;
        const float o = gg[0] * outc[t] + gg[1] * outf[t] + gg[2] * outs[t];
        g_o[(size_t)(b * S_ + s) * D_ + h * DH_ + t] = o;
    }
}

// ---------------- launch ----------------
extern "C" void kernel_launch(void* const* d_in, const int* in_sizes, int n_in,
                              void* d_out, int out_size) {
    (void)in_sizes; (void)n_in; (void)out_size;
    const float* x     = (const float*)d_in[0];
    // d_in[1] = ve (unused by the reference math)
    const float* x0    = (const float*)d_in[2];
    const float* lam   = (const float*)d_in[3];
    const float* Wq    = (const float*)d_in[4];
    const float* Wk    = (const float*)d_in[5];
    const float* Wv    = (const float*)d_in[6];
    const float* pos_k = (const float*)d_in[7];
    const float* pos_v = (const float*)d_in[8];
    const float* Wck   = (const float*)d_in[9];
    const float* Wcv   = (const float*)d_in[10];
    const float* mem_k = (const float*)d_in[11];
    const float* mem_v = (const float*)d_in[12];
    const float* Wg    = (const float*)d_in[13];
    const float* Wo    = (const float*)d_in[14];
    const float* Wfc   = (const float*)d_in[15];
    const float* Wproj = (const float*)d_in[16];
    float* out = (float*)d_out;

    k_rms1<<<ROWS_, 256>>>(x, x0, lam);

    dim3 g1(D_ / 128, ROWS_ / 128);        // (8,16)
    gemm_q<<<g1, 256>>>(Wq);
    gemm_k<<<g1, 256>>>(Wk);
    gemm_v<<<g1, 256>>>(Wv);
    k_gate<<<ROWS_, 64>>>(Wg);

    k_compress<<<B_ * NB_ * H_, 64>>>(pos_k, pos_v, Wck, Wcv);
    k_memfill<<<(B_ * H_ * DH_ + 255) / 256, 256>>>(mem_k, mem_v);
    k_rope<<<(B_ * S_ * H_ * 32) / 256, 256>>>();

    k_attn<<<B_ * H_ * S_, 256>>>();

    gemm_o<<<g1, 256>>>(Wo);               // x1 = xr + o@Wo
    k_rms2<<<ROWS_, 256>>>();              // m = rmsnorm(x1)

    dim3 g2(FD_ / 128, ROWS_ / 128);       // (32,16)
    gemm_fc<<<g2, 256>>>(Wfc);             // act = relu(m@Wfc)^2
    gemm_proj<<<g1, 256>>>(Wproj, out);    // out = x1 + act@Wproj
}

// round 3
// speedup vs baseline: 1.7244x; 1.7244x over previous
#include <cuda_runtime.h>
#include <math.h>

// Problem constants (fixed shapes)
#define B_  2
#define S_  1024
#define D_  1024
#define H_  16
#define DH_ 64
#define NB_ 256
#define NC_ 257     // compressed keys = mem + 256 blocks
#define FD_ 4096
#define ROWS_ (B_*S_)   // 2048
#define FULLMASK 0xffffffffu

// ---------------- scratch (static device arrays; no allocation) ----------------
__device__ float g_xr[B_*S_*D_];
__device__ float g_h [B_*S_*D_];
__device__ float g_q [B_*S_*D_];
__device__ float g_k [B_*S_*D_];
__device__ float g_v [B_*S_*D_];
__device__ float g_qr[B_*S_*D_];
__device__ float g_kr[B_*S_*D_];
__device__ float g_kc[B_*NC_*H_*DH_];
__device__ float g_vc[B_*NC_*H_*DH_];
__device__ float g_gate[B_*S_*48];
__device__ float g_o [B_*S_*D_];
__device__ float g_x1[B_*S_*D_];
__device__ float g_m [B_*S_*D_];
__device__ float g_act[B_*S_*FD_];
__device__ float g_ctab[S_*32];
__device__ float g_stab[S_*32];

// ---------------- packed fp32x2 FMA ----------------
__device__ __forceinline__ void ffma2(unsigned long long &acc, unsigned long long a, unsigned long long b) {
    asm("fma.rn.f32x2 %0, %1, %2, %0;" : "+l"(acc) : "l"(a), "l"(b));
}
__device__ __forceinline__ float2 unpack2(unsigned long long v) {
    float2 f;
    asm("mov.b64 {%0,%1}, %2;" : "=f"(f.x), "=f"(f.y) : "l"(v));
    return f;
}

// ---------------- K1: xr = l0*x + l1*x0 ; h = rmsnorm(xr) ----------------
__global__ void k_rms1(const float* __restrict__ x, const float* __restrict__ x0,
                       const float* __restrict__ lam) {
    const int row = blockIdx.x;
    const int t = threadIdx.x;
    const float l0 = lam[0], l1 = lam[1];
    const size_t base = (size_t)row * D_;
    __shared__ float red[8];
    __shared__ float s_inv;
    float ss = 0.f;
    for (int i = t; i < D_; i += 256) {
        float v = l0 * x[base + i] + l1 * x0[base + i];
        g_xr[base + i] = v;
        ss += v * v;
    }
#pragma unroll
    for (int o = 16; o; o >>= 1) ss += __shfl_xor_sync(FULLMASK, ss, o);
    if ((t & 31) == 0) red[t >> 5] = ss;
    __syncthreads();
    if (t == 0) {
        float tot = 0.f;
        for (int w = 0; w < 8; w++) tot += red[w];
        s_inv = rsqrtf(tot / (float)D_ + 1e-6f);
    }
    __syncthreads();
    const float inv = s_inv;
    for (int i = t; i < D_; i += 256) g_h[base + i] = g_xr[base + i] * inv;
}

__global__ void k_rms2() {
    const int row = blockIdx.x;
    const int t = threadIdx.x;
    const size_t base = (size_t)row * D_;
    __shared__ float red[8];
    __shared__ float s_inv;
    float ss = 0.f;
    for (int i = t; i < D_; i += 256) { float v = g_x1[base + i]; ss += v * v; }
#pragma unroll
    for (int o = 16; o; o >>= 1) ss += __shfl_xor_sync(FULLMASK, ss, o);
    if ((t & 31) == 0) red[t >> 5] = ss;
    __syncthreads();
    if (t == 0) {
        float tot = 0.f;
        for (int w = 0; w < 8; w++) tot += red[w];
        s_inv = rsqrtf(tot / (float)D_ + 1e-6f);
    }
    __syncthreads();
    const float inv = s_inv;
    for (int i = t; i < D_; i += 256) g_m[base + i] = g_x1[base + i] * inv;
}

// ---------------- SGEMM: C[M,N] = A[M,K] @ B[K,N] (+epilogue) ----------------
// 128x128 tile, BK=8, 256 threads, 8x8 per thread via f32x2 packed FMA.
// Double-buffered smem. A tile stored as duplicated pairs so LDS.64 = (a,a).
// EPI: 0 = store, 1 = store C=AB+Add, 2 = store relu(AB)^2
template <int EPI>
__device__ __forceinline__ void sgemm_body(const float* __restrict__ A,
                                           const float* __restrict__ B,
                                           float* __restrict__ C,
                                           const float* __restrict__ Add,
                                           int M, int N, int K) {
    __shared__ float As2[2][8][256];   // [buf][kk][2*row + {0,1}] duplicated
    __shared__ float Bs [2][8][128];
    const int tid = threadIdx.x;
    const int bx = blockIdx.x, by = blockIdx.y;
    const int aRow = tid >> 1;          // 0..127
    const int aCol = (tid & 1) << 2;    // 0 or 4
    const int bRow = tid >> 5;          // 0..7
    const int bCol = (tid & 31) << 2;   // 0..124
    const int tr = (tid >> 4) << 3;     // 0..120 step 8
    const int tc = (tid & 15) << 3;     // 0..120 step 8

    unsigned long long acc[8][4];
#pragma unroll
    for (int i = 0; i < 8; i++)
#pragma unroll
        for (int j = 0; j < 4; j++) acc[i][j] = 0ull;

    const float* Ap = A + (size_t)(by * 128 + aRow) * K + aCol;
    const float* Bp = B + (size_t)bRow * N + bx * 128 + bCol;

    // preload tile 0
    {
        float4 a4 = *(const float4*)(Ap);
        float4 b4 = *(const float4*)(Bp);
        *(float2*)&As2[0][aCol + 0][2 * aRow] = make_float2(a4.x, a4.x);
        *(float2*)&As2[0][aCol + 1][2 * aRow] = make_float2(a4.y, a4.y);
        *(float2*)&As2[0][aCol + 2][2 * aRow] = make_float2(a4.z, a4.z);
        *(float2*)&As2[0][aCol + 3][2 * aRow] = make_float2(a4.w, a4.w);
        *(float4*)&Bs[0][bRow][bCol] = b4;
    }
    __syncthreads();

    int buf = 0;
    for (int k0 = 8; k0 < K; k0 += 8) {
        float4 a4 = *(const float4*)(Ap + k0);
        float4 b4 = *(const float4*)(Bp + (size_t)k0 * N);
#pragma unroll
        for (int kk = 0; kk < 8; kk++) {
            const float* ab = &As2[buf][kk][2 * tr];
            const float* bb = &Bs [buf][kk][tc];
            ulonglong2 A01 = *(const ulonglong2*)(ab);
            ulonglong2 A23 = *(const ulonglong2*)(ab + 4);
            ulonglong2 A45 = *(const ulonglong2*)(ab + 8);
            ulonglong2 A67 = *(const ulonglong2*)(ab + 12);
            ulonglong2 B01 = *(const ulonglong2*)(bb);
            ulonglong2 B23 = *(const ulonglong2*)(bb + 4);
            unsigned long long ad[8] = {A01.x, A01.y, A23.x, A23.y, A45.x, A45.y, A67.x, A67.y};
            unsigned long long bd[4] = {B01.x, B01.y, B23.x, B23.y};
#pragma unroll
            for (int i = 0; i < 8; i++)
#pragma unroll
                for (int j = 0; j < 4; j++) ffma2(acc[i][j], ad[i], bd[j]);
        }
        const int nb = buf ^ 1;
        *(float2*)&As2[nb][aCol + 0][2 * aRow] = make_float2(a4.x, a4.x);
        *(float2*)&As2[nb][aCol + 1][2 * aRow] = make_float2(a4.y, a4.y);
        *(float2*)&As2[nb][aCol + 2][2 * aRow] = make_float2(a4.z, a4.z);
        *(float2*)&As2[nb][aCol + 3][2 * aRow] = make_float2(a4.w, a4.w);
        *(float4*)&Bs[nb][bRow][bCol] = b4;
        __syncthreads();
        buf = nb;
    }
    // last tile
#pragma unroll
    for (int kk = 0; kk < 8; kk++) {
        const float* ab = &As2[buf][kk][2 * tr];
        const float* bb = &Bs [buf][kk][tc];
        ulonglong2 A01 = *(const ulonglong2*)(ab);
        ulonglong2 A23 = *(const ulonglong2*)(ab + 4);
        ulonglong2 A45 = *(const ulonglong2*)(ab + 8);
        ulonglong2 A67 = *(const ulonglong2*)(ab + 12);
        ulonglong2 B01 = *(const ulonglong2*)(bb);
        ulonglong2 B23 = *(const ulonglong2*)(bb + 4);
        unsigned long long ad[8] = {A01.x, A01.y, A23.x, A23.y, A45.x, A45.y, A67.x, A67.y};
        unsigned long long bd[4] = {B01.x, B01.y, B23.x, B23.y};
#pragma unroll
        for (int i = 0; i < 8; i++)
#pragma unroll
            for (int j = 0; j < 4; j++) ffma2(acc[i][j], ad[i], bd[j]);
    }

#pragma unroll
    for (int i = 0; i < 8; i++) {
        const int row = by * 128 + tr + i;
#pragma unroll
        for (int jp = 0; jp < 4; jp += 2) {
            size_t idx = (size_t)row * N + bx * 128 + tc + jp * 2;
            float2 p0 = unpack2(acc[i][jp]);
            float2 p1 = unpack2(acc[i][jp + 1]);
            float4 v;
            v.x = p0.x; v.y = p0.y; v.z = p1.x; v.w = p1.y;
            if (EPI == 1) {
                float4 ad4 = *(const float4*)(Add + idx);
                v.x += ad4.x; v.y += ad4.y; v.z += ad4.z; v.w += ad4.w;
            } else if (EPI == 2) {
                v.x = fmaxf(v.x, 0.f); v.x *= v.x;
                v.y = fmaxf(v.y, 0.f); v.y *= v.y;
                v.z = fmaxf(v.z, 0.f); v.z *= v.z;
                v.w = fmaxf(v.w, 0.f); v.w *= v.w;
            }
            *(float4*)(C + idx) = v;
        }
    }
}

__global__ void __launch_bounds__(256, 2) gemm_qkv(const float* __restrict__ Wq,
                                                   const float* __restrict__ Wk,
                                                   const float* __restrict__ Wv) {
    const int z = blockIdx.z;
    const float* W = (z == 0) ? Wq : (z == 1) ? Wk : Wv;
    float* Cp = (z == 0) ? g_q : (z == 1) ? g_k : g_v;
    sgemm_body<0>(g_h, W, Cp, nullptr, ROWS_, D_, D_);
}
__global__ void __launch_bounds__(256, 2) gemm_o(const float* __restrict__ W) {
    sgemm_body<1>(g_o, W, g_x1, g_xr, ROWS_, D_, D_);
}
__global__ void __launch_bounds__(256, 2) gemm_fc(const float* __restrict__ W) {
    sgemm_body<2>(g_m, W, g_act, nullptr, ROWS_, FD_, D_);
}
__global__ void __launch_bounds__(256, 2) gemm_proj(const float* __restrict__ W, float* __restrict__ out) {
    sgemm_body<1>(g_act, W, out, g_x1, ROWS_, D_, FD_);
}

// ---------------- gates: g = sigmoid(h @ Wg), Wg (D,48) ----------------
__global__ void k_gate(const float* __restrict__ Wg) {
    const int row = blockIdx.x;
    const int t = threadIdx.x;   // 64 threads
    __shared__ float hrow[D_];
    for (int i = t; i < D_; i += 64) hrow[i] = g_h[(size_t)row * D_ + i];
    __syncthreads();
    if (t < 48) {
        float a = 0.f;
        for (int kk = 0; kk < D_; kk++) a += hrow[kk] * Wg[kk * 48 + t];
        g_gate[(size_t)row * 48 + t] = 1.f / (1.f + expf(-a));
    }
}

// ---------------- block compression: kc/vc for n>=1 ----------------
__global__ void k_compress(const float* __restrict__ pos_k, const float* __restrict__ pos_v,
                           const float* __restrict__ Wck, const float* __restrict__ Wcv) {
    const int idx = blockIdx.x;   // B*NB*H = 8192
    const int h = idx & (H_ - 1);
    const int n = (idx >> 4) & (NB_ - 1);
    const int b = idx >> 12;
    const int t = threadIdx.x;    // 64
    __shared__ float kb[256], vb[256];
    for (int r = t; r < 256; r += 64) {
        const int sp = r >> 6, d = r & 63;
        const int s = n * 4 + sp;
        const size_t src = ((size_t)(b * S_ + s) * H_ + h) * DH_ + d;
        kb[r] = g_k[src] + pos_k[(h * 4 + sp) * DH_ + d];
        vb[r] = g_v[src] + pos_v[(h * 4 + sp) * DH_ + d];
    }
    __syncthreads();
    float ak = 0.f, av = 0.f;
    for (int r = 0; r < 256; r++) {
        ak += kb[r] * Wck[r * DH_ + t];
        av += vb[r] * Wcv[r * DH_ + t];
    }
    const size_t dst = ((size_t)(b * NC_ + (n + 1)) * H_ + h) * DH_ + t;
    g_kc[dst] = ak;
    g_vc[dst] = av;
}

__global__ void k_memfill(const float* __restrict__ mem_k, const float* __restrict__ mem_v) {
    const int i = blockIdx.x * blockDim.x + threadIdx.x;  // B*H*DH = 2048
    if (i >= B_ * H_ * DH_) return;
    const int d = i & 63, h = (i >> 6) & (H_ - 1), b = i >> 10;
    const size_t dst = ((size_t)(b * NC_ + 0) * H_ + h) * DH_ + d;
    g_kc[dst] = mem_k[h * DH_ + d];
    g_vc[dst] = mem_v[h * DH_ + d];
}

// ---------------- trig table + RoPE ----------------
__global__ void k_trig() {
    const int i = blockIdx.x * blockDim.x + threadIdx.x;  // S*32
    if (i >= S_ * 32) return;
    const int p = i & 31;
    const int s = i >> 5;
    // inv = 10000^(-p/32) = exp2(-p * log2(10000)/32)
    const float inv = exp2f(-(float)p * (13.287712379549449f / 32.f));
    const float tt = (float)s * inv;
    g_ctab[i] = cosf(tt);
    g_stab[i] = sinf(tt);
}

__global__ void k_rope() {
    const int i = blockIdx.x * blockDim.x + threadIdx.x;  // B*S*H*32
    if (i >= B_ * S_ * H_ * 32) return;
    const int p = i & 31;
    const int h = (i >> 5) & (H_ - 1);
    const int s = (i >> 9) & (S_ - 1);
    const int b = i >> 19;
    const float c  = g_ctab[s * 32 + p];
    const float sn = g_stab[s * 32 + p];
    const size_t base = ((size_t)(b * S_ + s) * H_ + h) * DH_;
    float q1 = g_q[base + p], q2 = g_q[base + 32 + p];
    g_qr[base + p]      = q1 * c - q2 * sn;
    g_qr[base + 32 + p] = q1 * sn + q2 * c;
    float k1 = g_k[base + p], k2 = g_k[base + 32 + p];
    g_kr[base + p]      = k1 * c - k2 * sn;
    g_kr[base + 32 + p] = k1 * sn + k2 * c;
}

// ---------------- attention: warp-per-query, 8 queries per block ----------------
__device__ __forceinline__ float dot64(const float4* __restrict__ a, const float4* __restrict__ b) {
    float s = 0.f;
#pragma unroll
    for (int d = 0; d < 16; d++) {
        float4 x = a[d], y = b[d];
        s += x.x * y.x + x.y * y.y + x.z * y.z + x.w * y.w;
    }
    return s;
}

__global__ void __launch_bounds__(256) k_attn2() {
    const int blk = blockIdx.x;            // B*H*(S/8) = 4096
    const int s0 = (blk & 127) << 3;
    const int h = (blk >> 7) & (H_ - 1);
    const int b = blk >> 11;
    const int w = threadIdx.x >> 5;        // warp = query within tile
    const int l = threadIdx.x & 31;
    const int s = s0 + w;

    __shared__ float qs[8][64];
    __shared__ float qrs[8][64];
    __shared__ float sc[8][260];

    const size_t qbase = ((size_t)(b * S_ + s) * H_ + h) * DH_;
    qs [w][l]      = g_q [qbase + l];
    qs [w][l + 32] = g_q [qbase + 32 + l];
    qrs[w][l]      = g_qr[qbase + l];
    qrs[w][l + 32] = g_qr[qbase + 32 + l];
    __syncwarp();

    const int nvisB = (s >= 3) ? (((s - 3) >> 2) + 1) : 0;
    const int nk = nvisB + 1;
    const float4* q4  = (const float4*)qs[w];
    const float4* qr4 = (const float4*)qrs[w];

    // ---- compressed scores (lane-strided keys) ----
    float raw[9];
    int cnt = 0;
    float mymax = -1e30f;
    for (int n = l; n < nk; n += 32) {
        const float4* k4 = (const float4*)(g_kc + ((size_t)(b * NC_ + n) * H_ + h) * DH_);
        float a = dot64(q4, k4) * 0.125f;
        raw[cnt++] = a;
        mymax = fmaxf(mymax, a);
    }
#pragma unroll
    for (int o = 16; o; o >>= 1) mymax = fmaxf(mymax, __shfl_xor_sync(FULLMASK, mymax, o));
    float mysum = 0.f;
    {
        int i = 0;
        for (int n = l; n < nk; n += 32, i++) {
            float e = expf(raw[i] - mymax);
            raw[i] = e;
            sc[w][n] = e;
            mysum += e;
        }
    }
#pragma unroll
    for (int o = 16; o; o >>= 1) mysum += __shfl_xor_sync(FULLMASK, mysum, o);
    const float rcs = 1.f / mysum;

    // ---- top-4 blocks (exclude n==0 mem slot); ties -> lower index ----
    float tv[4] = {-1.f, -1.f, -1.f, -1.f};
    int   ti[4] = {0, 0, 0, 0};
    {
        int i = 0;
        for (int n = l; n < nk; n += 32, i++) {
            if (n >= 1) {
                float vI = raw[i];
                if (vI > tv[3]) {
                    int p2 = 3;
                    while (p2 > 0 && vI > tv[p2 - 1]) {
                        tv[p2] = tv[p2 - 1]; ti[p2] = ti[p2 - 1]; p2--;
                    }
                    tv[p2] = vI; ti[p2] = n - 1;
                }
            }
        }
    }
#pragma unroll
    for (int off = 16; off; off >>= 1) {
        float ov[4]; int oi[4];
#pragma unroll
        for (int m = 0; m < 4; m++) {
            ov[m] = __shfl_xor_sync(FULLMASK, tv[m], off);
            oi[m] = __shfl_xor_sync(FULLMASK, ti[m], off);
        }
#pragma unroll
        for (int m = 0; m < 4; m++) {
            float v2 = ov[m]; int i2 = oi[m];
            if ((v2 > tv[3]) || (v2 == tv[3] && i2 < ti[3])) {
                int p2 = 3;
                while (p2 > 0 && ((v2 > tv[p2 - 1]) || (v2 == tv[p2 - 1] && i2 < ti[p2 - 1]))) {
                    tv[p2] = tv[p2 - 1]; ti[p2] = ti[p2 - 1]; p2--;
                }
                tv[p2] = v2; ti[p2] = i2;
            }
        }
    }

    // ---- cout (PV over compressed values) ----
    float oc0 = 0.f, oc1 = 0.f;
    {
        const float* vr = g_vc + ((size_t)(b * NC_) * H_ + h) * DH_;
        for (int n = 0; n < nk; n++) {
            float pn = sc[w][n];
            const float* p = vr + (size_t)n * (H_ * DH_);
            oc0 += pn * p[l];
            oc1 += pn * p[l + 32];
        }
    }
    oc0 *= rcs; oc1 *= rcs;

    // ---- fine: 20 gathered keys (4 selected blocks + own block) ----
    float fe = 0.f;
    int fkp = 0;
    {
        float fs = -1e30f;
        if (l < 20) {
            const int m = l >> 2, sp = l & 3;
            const int blk2 = (m == 4) ? (s >> 2) : ti[m];
            fkp = blk2 * 4 + sp;
            const bool vis = ((m == 4) || (tv[m] > 0.f)) && (fkp <= s);
            if (vis) {
                const float4* k4 = (const float4*)(g_kr + ((size_t)(b * S_ + fkp) * H_ + h) * DH_);
                fs = dot64(qr4, k4) * 0.125f;
            }
        }
        float fmx = fs;
#pragma unroll
        for (int o = 16; o; o >>= 1) fmx = fmaxf(fmx, __shfl_xor_sync(FULLMASK, fmx, o));
        fe = (fs > -1e29f) ? expf(fs - fmx) : 0.f;
    }
    float fsum = fe;
#pragma unroll
    for (int o = 16; o; o >>= 1) fsum += __shfl_xor_sync(FULLMASK, fsum, o);
    const float rcf = 1.f / fsum;

    float of0 = 0.f, of1 = 0.f;
    for (int j = 0; j < 20; j++) {
        float pj = __shfl_sync(FULLMASK, fe, j);
        int kj   = __shfl_sync(FULLMASK, fkp, j);
        const float* p = g_v + ((size_t)(b * S_ + kj) * H_ + h) * DH_;
        of0 += pj * p[l];
        of1 += pj * p[l + 32];
    }
    of0 *= rcf; of1 *= rcf;

    // ---- sliding window 32 ----
    float se = 0.f;
    {
        const int pos = s - l;
        float ssv = -1e30f;
        if (pos >= 0) {
            const float4* k4 = (const float4*)(g_kr + ((size_t)(b * S_ + pos) * H_ + h) * DH_);
            ssv = dot64(qr4, k4) * 0.125f;
        }
        float smx = ssv;
#pragma unroll
        for (int o = 16; o; o >>= 1) smx = fmaxf(smx, __shfl_xor_sync(FULLMASK, smx, o));
        se = (ssv > -1e29f) ? expf(ssv - smx) : 0.f;
    }
    float ssum = se;
#pragma unroll
    for (int o = 16; o; o >>= 1) ssum += __shfl_xor_sync(FULLMASK, ssum, o);
    const float rcw = 1.f / ssum;

    float os0 = 0.f, os1 = 0.f;
    {
        const int wmax = s < 31 ? s : 31;
        for (int w2 = 0; w2 <= wmax; w2++) {
            float pj = __shfl_sync(FULLMASK, se, w2);
            const float* p = g_v + ((size_t)(b * S_ + (s - w2)) * H_ + h) * DH_;
            os0 += pj * p[l];
            os1 += pj * p[l + 32];
        }
    }
    os0 *= rcw; os1 *= rcw;

    // ---- gate + write ----
    const float* gg = g_gate + (size_t)(b * S_ + s) * 48 + h * 3;
    const float g0 = gg[0], g1 = gg[1], g2 = gg[2];
    float* op = g_o + (size_t)(b * S_ + s) * D_ + h * DH_;
    op[l]      = g0 * oc0 + g1 * of0 + g2 * os0;
    op[l + 32] = g0 * oc1 + g1 * of1 + g2 * os1;
}

// ---------------- launch ----------------
extern "C" void kernel_launch(void* const* d_in, const int* in_sizes, int n_in,
                              void* d_out, int out_size) {
    (void)in_sizes; (void)n_in; (void)out_size;
    const float* x     = (const float*)d_in[0];
    const float* x0    = (const float*)d_in[2];
    const float* lam   = (const float*)d_in[3];
    const float* Wq    = (const float*)d_in[4];
    const float* Wk    = (const float*)d_in[5];
    const float* Wv    = (const float*)d_in[6];
    const float* pos_k = (const float*)d_in[7];
    const float* pos_v = (const float*)d_in[8];
    const float* Wck   = (const float*)d_in[9];
    const float* Wcv   = (const float*)d_in[10];
    const float* mem_k = (const float*)d_in[11];
    const float* mem_v = (const float*)d_in[12];
    const float* Wg    = (const float*)d_in[13];
    const float* Wo    = (const float*)d_in[14];
    const float* Wfc   = (const float*)d_in[15];
    const float* Wproj = (const float*)d_in[16];
    float* out = (float*)d_out;

    k_trig<<<(S_ * 32) / 256, 256>>>();
    k_rms1<<<ROWS_, 256>>>(x, x0, lam);

    dim3 gqkv(D_ / 128, ROWS_ / 128, 3);   // (8,16,3)
    gemm_qkv<<<gqkv, 256>>>(Wq, Wk, Wv);
    k_gate<<<ROWS_, 64>>>(Wg);

    k_compress<<<B_ * NB_ * H_, 64>>>(pos_k, pos_v, Wck, Wcv);
    k_memfill<<<(B_ * H_ * DH_ + 255) / 256, 256>>>(mem_k, mem_v);
    k_rope<<<(B_ * S_ * H_ * 32) / 256, 256>>>();

    k_attn2<<<B_ * H_ * (S_ / 8), 256>>>();

    dim3 g1(D_ / 128, ROWS_ / 128);        // (8,16)
    gemm_o<<<g1, 256>>>(Wo);               // x1 = xr + o@Wo
    k_rms2<<<ROWS_, 256>>>();              // m = rmsnorm(x1)

    dim3 g2(FD_ / 128, ROWS_ / 128);       // (32,16)
    gemm_fc<<<g2, 256>>>(Wfc);             // act = relu(m@Wfc)^2
    gemm_proj<<<g1, 256>>>(Wproj, out);    // out = x1 + act@Wproj
}

// round 8
// speedup vs baseline: 2.1911x; 1.2706x over previous
#include <cuda_runtime.h>
#include <math.h>

// Problem constants (fixed shapes)
#define B_  2
#define S_  1024
#define D_  1024
#define H_  16
#define DH_ 64
#define NB_ 256
#define NC_ 257     // compressed keys = mem + 256 blocks
#define FD_ 4096
#define ROWS_ (B_*S_)   // 2048
#define FULLMASK 0xffffffffu

// ---------------- scratch (static device arrays; no allocation) ----------------
__device__ float g_xr[B_*S_*D_];
__device__ float g_h [B_*S_*D_];
__device__ float g_q [B_*S_*D_];
__device__ float g_k [B_*S_*D_];
__device__ float g_v [B_*S_*D_];
__device__ float g_qr[B_*S_*D_];
__device__ float g_kr[B_*S_*D_];
__device__ float g_kc[B_*NC_*H_*DH_];
__device__ float g_vc[B_*NC_*H_*DH_];
__device__ float g_gate[B_*S_*48];
__device__ float g_o [B_*S_*D_];
__device__ float g_x1[B_*S_*D_];
__device__ float g_m [B_*S_*D_];
__device__ float g_act[B_*S_*FD_];
__device__ float g_ctab[S_*32];
__device__ float g_stab[S_*32];

// ---------------- packed fp32x2 FMA ----------------
__device__ __forceinline__ void ffma2(unsigned long long &acc, unsigned long long a, unsigned long long b) {
    asm("fma.rn.f32x2 %0, %1, %2, %0;" : "+l"(acc) : "l"(a), "l"(b));
}
__device__ __forceinline__ float2 unpack2(unsigned long long v) {
    float2 f;
    asm("mov.b64 {%0,%1}, %2;" : "=f"(f.x), "=f"(f.y) : "l"(v));
    return f;
}

// ---------------- K1: xr = l0*x + l1*x0 ; h = rmsnorm(xr) ----------------
__global__ void k_rms1(const float* __restrict__ x, const float* __restrict__ x0,
                       const float* __restrict__ lam) {
    const int row = blockIdx.x;
    const int t = threadIdx.x;
    const float l0 = lam[0], l1 = lam[1];
    const size_t base = (size_t)row * D_;
    __shared__ float red[8];
    __shared__ float s_inv;
    float ss = 0.f;
    for (int i = t; i < D_; i += 256) {
        float v = l0 * x[base + i] + l1 * x0[base + i];
        g_xr[base + i] = v;
        ss += v * v;
    }
#pragma unroll
    for (int o = 16; o; o >>= 1) ss += __shfl_xor_sync(FULLMASK, ss, o);
    if ((t & 31) == 0) red[t >> 5] = ss;
    __syncthreads();
    if (t == 0) {
        float tot = 0.f;
        for (int w = 0; w < 8; w++) tot += red[w];
        s_inv = rsqrtf(tot / (float)D_ + 1e-6f);
    }
    __syncthreads();
    const float inv = s_inv;
    for (int i = t; i < D_; i += 256) g_h[base + i] = g_xr[base + i] * inv;
}

__global__ void k_rms2() {
    const int row = blockIdx.x;
    const int t = threadIdx.x;
    const size_t base = (size_t)row * D_;
    __shared__ float red[8];
    __shared__ float s_inv;
    float ss = 0.f;
    for (int i = t; i < D_; i += 256) { float v = g_x1[base + i]; ss += v * v; }
#pragma unroll
    for (int o = 16; o; o >>= 1) ss += __shfl_xor_sync(FULLMASK, ss, o);
    if ((t & 31) == 0) red[t >> 5] = ss;
    __syncthreads();
    if (t == 0) {
        float tot = 0.f;
        for (int w = 0; w < 8; w++) tot += red[w];
        s_inv = rsqrtf(tot / (float)D_ + 1e-6f);
    }
    __syncthreads();
    const float inv = s_inv;
    for (int i = t; i < D_; i += 256) g_m[base + i] = g_x1[base + i] * inv;
}

// ================= fp32 SGEMM (f32x2) — used for Q/K/V (selection-critical) =================
template <int EPI>
__device__ __forceinline__ void sgemm_body(const float* __restrict__ A,
                                           const float* __restrict__ B,
                                           float* __restrict__ C,
                                           const float* __restrict__ Add,
                                           int M, int N, int K) {
    __shared__ float As2[2][8][256];
    __shared__ float Bs [2][8][128];
    const int tid = threadIdx.x;
    const int bx = blockIdx.x, by = blockIdx.y;
    const int aRow = tid >> 1;
    const int aCol = (tid & 1) << 2;
    const int bRow = tid >> 5;
    const int bCol = (tid & 31) << 2;
    const int tr = (tid >> 4) << 3;
    const int tc = (tid & 15) << 3;

    unsigned long long acc[8][4];
#pragma unroll
    for (int i = 0; i < 8; i++)
#pragma unroll
        for (int j = 0; j < 4; j++) acc[i][j] = 0ull;

    const float* Ap = A + (size_t)(by * 128 + aRow) * K + aCol;
    const float* Bp = B + (size_t)bRow * N + bx * 128 + bCol;

    {
        float4 a4 = *(const float4*)(Ap);
        float4 b4 = *(const float4*)(Bp);
        *(float2*)&As2[0][aCol + 0][2 * aRow] = make_float2(a4.x, a4.x);
        *(float2*)&As2[0][aCol + 1][2 * aRow] = make_float2(a4.y, a4.y);
        *(float2*)&As2[0][aCol + 2][2 * aRow] = make_float2(a4.z, a4.z);
        *(float2*)&As2[0][aCol + 3][2 * aRow] = make_float2(a4.w, a4.w);
        *(float4*)&Bs[0][bRow][bCol] = b4;
    }
    __syncthreads();

    int buf = 0;
    for (int k0 = 8; k0 < K; k0 += 8) {
        float4 a4 = *(const float4*)(Ap + k0);
        float4 b4 = *(const float4*)(Bp + (size_t)k0 * N);
#pragma unroll
        for (int kk = 0; kk < 8; kk++) {
            const float* ab = &As2[buf][kk][2 * tr];
            const float* bb = &Bs [buf][kk][tc];
            ulonglong2 A01 = *(const ulonglong2*)(ab);
            ulonglong2 A23 = *(const ulonglong2*)(ab + 4);
            ulonglong2 A45 = *(const ulonglong2*)(ab + 8);
            ulonglong2 A67 = *(const ulonglong2*)(ab + 12);
            ulonglong2 B01 = *(const ulonglong2*)(bb);
            ulonglong2 B23 = *(const ulonglong2*)(bb + 4);
            unsigned long long ad[8] = {A01.x, A01.y, A23.x, A23.y, A45.x, A45.y, A67.x, A67.y};
            unsigned long long bd[4] = {B01.x, B01.y, B23.x, B23.y};
#pragma unroll
            for (int i = 0; i < 8; i++)
#pragma unroll
                for (int j = 0; j < 4; j++) ffma2(acc[i][j], ad[i], bd[j]);
        }
        const int nb = buf ^ 1;
        *(float2*)&As2[nb][aCol + 0][2 * aRow] = make_float2(a4.x, a4.x);
        *(float2*)&As2[nb][aCol + 1][2 * aRow] = make_float2(a4.y, a4.y);
        *(float2*)&As2[nb][aCol + 2][2 * aRow] = make_float2(a4.z, a4.z);
        *(float2*)&As2[nb][aCol + 3][2 * aRow] = make_float2(a4.w, a4.w);
        *(float4*)&Bs[nb][bRow][bCol] = b4;
        __syncthreads();
        buf = nb;
    }
#pragma unroll
    for (int kk = 0; kk < 8; kk++) {
        const float* ab = &As2[buf][kk][2 * tr];
        const float* bb = &Bs [buf][kk][tc];
        ulonglong2 A01 = *(const ulonglong2*)(ab);
        ulonglong2 A23 = *(const ulonglong2*)(ab + 4);
        ulonglong2 A45 = *(const ulonglong2*)(ab + 8);
        ulonglong2 A67 = *(const ulonglong2*)(ab + 12);
        ulonglong2 B01 = *(const ulonglong2*)(bb);
        ulonglong2 B23 = *(const ulonglong2*)(bb + 4);
        unsigned long long ad[8] = {A01.x, A01.y, A23.x, A23.y, A45.x, A45.y, A67.x, A67.y};
        unsigned long long bd[4] = {B01.x, B01.y, B23.x, B23.y};
#pragma unroll
        for (int i = 0; i < 8; i++)
#pragma unroll
            for (int j = 0; j < 4; j++) ffma2(acc[i][j], ad[i], bd[j]);
    }

#pragma unroll
    for (int i = 0; i < 8; i++) {
        const int row = by * 128 + tr + i;
#pragma unroll
        for (int jp = 0; jp < 4; jp += 2) {
            size_t idx = (size_t)row * N + bx * 128 + tc + jp * 2;
            float2 p0 = unpack2(acc[i][jp]);
            float2 p1 = unpack2(acc[i][jp + 1]);
            float4 v;
            v.x = p0.x; v.y = p0.y; v.z = p1.x; v.w = p1.y;
            if (EPI == 1) {
                float4 ad4 = *(const float4*)(Add + idx);
                v.x += ad4.x; v.y += ad4.y; v.z += ad4.z; v.w += ad4.w;
            }
            *(float4*)(C + idx) = v;
        }
    }
}

__global__ void __launch_bounds__(256, 2) gemm_qkv(const float* __restrict__ Wq,
                                                   const float* __restrict__ Wk,
                                                   const float* __restrict__ Wv) {
    const int z = blockIdx.z;
    const float* W = (z == 0) ? Wq : (z == 1) ? Wk : Wv;
    float* Cp = (z == 0) ? g_q : (z == 1) ? g_k : g_v;
    sgemm_body<0>(g_h, W, Cp, nullptr, ROWS_, D_, D_);
}

// ================= 3xTF32 tensor-core GEMM (error-compensated, mma.sync m16n8k8) =================
// CTA tile 128x128, BK=32, 8 warps (2x4), warp tile 64x32, cp.async double buffer.
// Each operand split a = a_hi + a_lo (cvt.rna.tf32); acc += ah*bh + ah*bl + al*bh.
#define ASZ 4608    // 128*36
#define BSZ 4352    // 32*136
#define BUFSZ 8960  // ASZ+BSZ
#define SMEM_BYTES (2*BUFSZ*4)   // 71680

__device__ __forceinline__ void cp16(void* dst_smem, const void* src) {
    unsigned d = (unsigned)__cvta_generic_to_shared(dst_smem);
    asm volatile("cp.async.ca.shared.global [%0], [%1], 16;" :: "r"(d), "l"(src));
}

__device__ __forceinline__ unsigned tf32_rna(float x) {
    unsigned r;
    asm("cvt.rna.tf32.f32 %0, %1;" : "=r"(r) : "f"(x));
    return r;
}
__device__ __forceinline__ void split_tf32(float x, unsigned &hi, unsigned &lo) {
    hi = tf32_rna(x);
    lo = tf32_rna(x - __uint_as_float(hi));
}

__device__ __forceinline__ void mma_tf32(float c[4], const unsigned a[4], const unsigned b[2]) {
    asm volatile(
        "mma.sync.aligned.m16n8k8.row.col.f32.tf32.tf32.f32 "
        "{%0,%1,%2,%3}, {%4,%5,%6,%7}, {%8,%9}, {%0,%1,%2,%3};"
        : "+f"(c[0]), "+f"(c[1]), "+f"(c[2]), "+f"(c[3])
        : "r"(a[0]), "r"(a[1]), "r"(a[2]), "r"(a[3]), "r"(b[0]), "r"(b[1]));
}

template <int EPI>
__device__ __forceinline__ void mma_gemm(const float* __restrict__ A,
                                         const float* __restrict__ Bm,
                                         float* __restrict__ C,
                                         const float* __restrict__ Add,
                                         int N, int K) {
    extern __shared__ float smem[];
    const int tid = threadIdx.x;
    const int warp = tid >> 5, lane = tid & 31;
    const int wm = warp >> 2, wn = warp & 3;
    const int g = lane >> 2, tg = lane & 3;
    const int tileM = blockIdx.y * 128, tileN = blockIdx.x * 128;

    float acc[4][4][4];
#pragma unroll
    for (int mt = 0; mt < 4; mt++)
#pragma unroll
        for (int nt = 0; nt < 4; nt++)
#pragma unroll
            for (int c = 0; c < 4; c++) acc[mt][nt][c] = 0.f;

    const int ar = tid >> 3, ac0 = (tid & 7) << 2;
    const int bk = tid >> 5, bn0 = (tid & 31) << 2;

    const int niter = K >> 5;

    {
        float* Ab = smem;
        float* Bb = smem + ASZ;
#pragma unroll
        for (int p = 0; p < 4; p++) {
            int r = ar + p * 32;
            cp16(Ab + r * 36 + ac0, A + (size_t)(tileM + r) * K + ac0);
        }
#pragma unroll
        for (int p = 0; p < 4; p++) {
            int kk = bk + p * 8;
            cp16(Bb + kk * 136 + bn0, Bm + (size_t)kk * N + tileN + bn0);
        }
        asm volatile("cp.async.commit_group;" ::: "memory");
    }

    for (int i = 0; i < niter; i++) {
        if (i + 1 < niter) {
            const int k0 = (i + 1) << 5;
            float* Ab = smem + ((i + 1) & 1) * BUFSZ;
            float* Bb = Ab + ASZ;
#pragma unroll
            for (int p = 0; p < 4; p++) {
                int r = ar + p * 32;
                cp16(Ab + r * 36 + ac0, A + (size_t)(tileM + r) * K + k0 + ac0);
            }
#pragma unroll
            for (int p = 0; p < 4; p++) {
                int kk = bk + p * 8;
                cp16(Bb + kk * 136 + bn0, Bm + (size_t)(k0 + kk) * N + tileN + bn0);
            }
            asm volatile("cp.async.commit_group;" ::: "memory");
            asm volatile("cp.async.wait_group 1;" ::: "memory");
        } else {
            asm volatile("cp.async.wait_group 0;" ::: "memory");
        }
        __syncthreads();

        const float* Ab = smem + (i & 1) * BUFSZ;
        const float* Bb = Ab + ASZ;
#pragma unroll
        for (int kt = 0; kt < 4; kt++) {
            unsigned afh[4][4], afl[4][4], bfh[4][2], bfl[4][2];
#pragma unroll
            for (int mt = 0; mt < 4; mt++) {
                const float* ap = Ab + (wm * 64 + mt * 16 + g) * 36 + kt * 8 + tg;
                split_tf32(ap[0],          afh[mt][0], afl[mt][0]);
                split_tf32(ap[8 * 36],     afh[mt][1], afl[mt][1]);
                split_tf32(ap[4],          afh[mt][2], afl[mt][2]);
                split_tf32(ap[8 * 36 + 4], afh[mt][3], afl[mt][3]);
            }
#pragma unroll
            for (int nt = 0; nt < 4; nt++) {
                const float* bp = Bb + (kt * 8 + tg) * 136 + wn * 32 + nt * 8 + g;
                split_tf32(bp[0],       bfh[nt][0], bfl[nt][0]);
                split_tf32(bp[4 * 136], bfh[nt][1], bfl[nt][1]);
            }
#pragma unroll
            for (int mt = 0; mt < 4; mt++)
#pragma unroll
                for (int nt = 0; nt < 4; nt++) {
                    mma_tf32(acc[mt][nt], afh[mt], bfl[nt]);  // hi*lo
                    mma_tf32(acc[mt][nt], afl[mt], bfh[nt]);  // lo*hi
                    mma_tf32(acc[mt][nt], afh[mt], bfh[nt]);  // hi*hi
                }
        }
        __syncthreads();
    }

#pragma unroll
    for (int mt = 0; mt < 4; mt++) {
#pragma unroll
        for (int nt = 0; nt < 4; nt++) {
            const int row = tileM + wm * 64 + mt * 16 + g;
            const int col = tileN + wn * 32 + nt * 8 + tg * 2;
            float2 v0 = make_float2(acc[mt][nt][0], acc[mt][nt][1]);
            float2 v1 = make_float2(acc[mt][nt][2], acc[mt][nt][3]);
            size_t i0 = (size_t)row * N + col;
            size_t i1 = (size_t)(row + 8) * N + col;
            if (EPI == 1) {
                float2 a0 = *(const float2*)(Add + i0);
                float2 a1 = *(const float2*)(Add + i1);
                v0.x += a0.x; v0.y += a0.y;
                v1.x += a1.x; v1.y += a1.y;
            } else if (EPI == 2) {
                v0.x = fmaxf(v0.x, 0.f); v0.x *= v0.x;
                v0.y = fmaxf(v0.y, 0.f); v0.y *= v0.y;
                v1.x = fmaxf(v1.x, 0.f); v1.x *= v1.x;
                v1.y = fmaxf(v1.y, 0.f); v1.y *= v1.y;
            }
            *(float2*)(C + i0) = v0;
            *(float2*)(C + i1) = v1;
        }
    }
}

__global__ void __launch_bounds__(256) gemm_o_t(const float* __restrict__ W) {
    mma_gemm<1>(g_o, W, g_x1, g_xr, D_, D_);
}
__global__ void __launch_bounds__(256) gemm_fc_t(const float* __restrict__ W) {
    mma_gemm<2>(g_m, W, g_act, nullptr, FD_, D_);
}
__global__ void __launch_bounds__(256) gemm_proj_t(const float* __restrict__ W, float* __restrict__ out) {
    mma_gemm<1>(g_act, W, out, g_x1, D_, FD_);
}

// ---------------- gates: tiled, 16 rows x 48 cols per block ----------------
__global__ void __launch_bounds__(768) k_gate2(const float* __restrict__ Wg) {
    __shared__ float sh[16 * 128];
    __shared__ float sw[128 * 48];
    const int t = threadIdx.x;
    const int r = t / 48, c = t % 48;
    const int row0 = blockIdx.x * 16;
    float acc = 0.f;
    for (int k0 = 0; k0 < D_; k0 += 128) {
        for (int i = t; i < 16 * 128; i += 768)
            sh[i] = g_h[(size_t)(row0 + (i >> 7)) * D_ + k0 + (i & 127)];
        for (int i = t; i < 128 * 48; i += 768)
            sw[i] = Wg[(size_t)(k0 + i / 48) * 48 + (i % 48)];
        __syncthreads();
        const float* hr = &sh[r * 128];
#pragma unroll 8
        for (int kk = 0; kk < 128; kk++) acc += hr[kk] * sw[kk * 48 + c];
        __syncthreads();
    }
    g_gate[(size_t)(row0 + r) * 48 + c] = 1.f / (1.f + expf(-acc));
}

// ---------------- block compression: kc/vc for n>=1 ----------------
__global__ void k_compress(const float* __restrict__ pos_k, const float* __restrict__ pos_v,
                           const float* __restrict__ Wck, const float* __restrict__ Wcv) {
    const int idx = blockIdx.x;   // B*NB*H = 8192
    const int h = idx & (H_ - 1);
    const int n = (idx >> 4) & (NB_ - 1);
    const int b = idx >> 12;
    const int t = threadIdx.x;    // 64
    __shared__ float kb[256], vb[256];
    for (int r = t; r < 256; r += 64) {
        const int sp = r >> 6, d = r & 63;
        const int s = n * 4 + sp;
        const size_t src = ((size_t)(b * S_ + s) * H_ + h) * DH_ + d;
        kb[r] = g_k[src] + pos_k[(h * 4 + sp) * DH_ + d];
        vb[r] = g_v[src] + pos_v[(h * 4 + sp) * DH_ + d];
    }
    __syncthreads();
    float ak = 0.f, av = 0.f;
    for (int r = 0; r < 256; r++) {
        ak += kb[r] * Wck[r * DH_ + t];
        av += vb[r] * Wcv[r * DH_ + t];
    }
    const size_t dst = ((size_t)(b * NC_ + (n + 1)) * H_ + h) * DH_ + t;
    g_kc[dst] = ak;
    g_vc[dst] = av;
}

__global__ void k_memfill(const float* __restrict__ mem_k, const float* __restrict__ mem_v) {
    const int i = blockIdx.x * blockDim.x + threadIdx.x;  // B*H*DH = 2048
    if (i >= B_ * H_ * DH_) return;
    const int d = i & 63, h = (i >> 6) & (H_ - 1), b = i >> 10;
    const size_t dst = ((size_t)(b * NC_ + 0) * H_ + h) * DH_ + d;
    g_kc[dst] = mem_k[h * DH_ + d];
    g_vc[dst] = mem_v[h * DH_ + d];
}

// ---------------- trig table + RoPE ----------------
__global__ void k_trig() {
    const int i = blockIdx.x * blockDim.x + threadIdx.x;  // S*32
    if (i >= S_ * 32) return;
    const int p = i & 31;
    const int s = i >> 5;
    const float inv = exp2f(-(float)p * (13.287712379549449f / 32.f));
    const float tt = (float)s * inv;
    g_ctab[i] = cosf(tt);
    g_stab[i] = sinf(tt);
}

__global__ void k_rope() {
    const int i = blockIdx.x * blockDim.x + threadIdx.x;  // B*S*H*32
    if (i >= B_ * S_ * H_ * 32) return;
    const int p = i & 31;
    const int h = (i >> 5) & (H_ - 1);
    const int s = (i >> 9) & (S_ - 1);
    const int b = i >> 19;
    const float c  = g_ctab[s * 32 + p];
    const float sn = g_stab[s * 32 + p];
    const size_t base = ((size_t)(b * S_ + s) * H_ + h) * DH_;
    float q1 = g_q[base + p], q2 = g_q[base + 32 + p];
    g_qr[base + p]      = q1 * c - q2 * sn;
    g_qr[base + 32 + p] = q1 * sn + q2 * c;
    float k1 = g_k[base + p], k2 = g_k[base + 32 + p];
    g_kr[base + p]      = k1 * c - k2 * sn;
    g_kr[base + 32 + p] = k1 * sn + k2 * c;
}

// ---------------- attention: warp-per-query, 8 queries per block ----------------
__device__ __forceinline__ float dot64(const float4* __restrict__ a, const float4* __restrict__ b) {
    float s = 0.f;
#pragma unroll
    for (int d = 0; d < 16; d++) {
        float4 x = a[d], y = b[d];
        s += x.x * y.x + x.y * y.y + x.z * y.z + x.w * y.w;
    }
    return s;
}

__global__ void __launch_bounds__(256) k_attn2() {
    const int blk = blockIdx.x;            // B*H*(S/8) = 4096
    const int s0 = (blk & 127) << 3;
    const int h = (blk >> 7) & (H_ - 1);
    const int b = blk >> 11;
    const int w = threadIdx.x >> 5;
    const int l = threadIdx.x & 31;
    const int s = s0 + w;

    __shared__ float qs[8][64];
    __shared__ float qrs[8][64];
    __shared__ float sc[8][260];

    const size_t qbase = ((size_t)(b * S_ + s) * H_ + h) * DH_;
    qs [w][l]      = g_q [qbase + l];
    qs [w][l + 32] = g_q [qbase + 32 + l];
    qrs[w][l]      = g_qr[qbase + l];
    qrs[w][l + 32] = g_qr[qbase + 32 + l];
    __syncwarp();

    const int nvisB = (s >= 3) ? (((s - 3) >> 2) + 1) : 0;
    const int nk = nvisB + 1;
    const float4* q4  = (const float4*)qs[w];
    const float4* qr4 = (const float4*)qrs[w];

    float raw[9];
    int cnt = 0;
    float mymax = -1e30f;
    for (int n = l; n < nk; n += 32) {
        const float4* k4 = (const float4*)(g_kc + ((size_t)(b * NC_ + n) * H_ + h) * DH_);
        float a = dot64(q4, k4) * 0.125f;
        raw[cnt++] = a;
        mymax = fmaxf(mymax, a);
    }
#pragma unroll
    for (int o = 16; o; o >>= 1) mymax = fmaxf(mymax, __shfl_xor_sync(FULLMASK, mymax, o));
    float mysum = 0.f;
    {
        int i = 0;
        for (int n = l; n < nk; n += 32, i++) {
            float e = expf(raw[i] - mymax);
            raw[i] = e;
            sc[w][n] = e;
            mysum += e;
        }
    }
#pragma unroll
    for (int o = 16; o; o >>= 1) mysum += __shfl_xor_sync(FULLMASK, mysum, o);
    const float rcs = 1.f / mysum;

    float tv[4] = {-1.f, -1.f, -1.f, -1.f};
    int   ti[4] = {0, 0, 0, 0};
    {
        int i = 0;
        for (int n = l; n < nk; n += 32, i++) {
            if (n >= 1) {
                float vI = raw[i];
                if (vI > tv[3]) {
                    int p2 = 3;
                    while (p2 > 0 && vI > tv[p2 - 1]) {
                        tv[p2] = tv[p2 - 1]; ti[p2] = ti[p2 - 1]; p2--;
                    }
                    tv[p2] = vI; ti[p2] = n - 1;
                }
            }
        }
    }
#pragma unroll
    for (int off = 16; off; off >>= 1) {
        float ov[4]; int oi[4];
#pragma unroll
        for (int m = 0; m < 4; m++) {
            ov[m] = __shfl_xor_sync(FULLMASK, tv[m], off);
            oi[m] = __shfl_xor_sync(FULLMASK, ti[m], off);
        }
#pragma unroll
        for (int m = 0; m < 4; m++) {
            float v2 = ov[m]; int i2 = oi[m];
            if ((v2 > tv[3]) || (v2 == tv[3] && i2 < ti[3])) {
                int p2 = 3;
                while (p2 > 0 && ((v2 > tv[p2 - 1]) || (v2 == tv[p2 - 1] && i2 < ti[p2 - 1]))) {
                    tv[p2] = tv[p2 - 1]; ti[p2] = ti[p2 - 1]; p2--;
                }
                tv[p2] = v2; ti[p2] = i2;
            }
        }
    }

    float oc0 = 0.f, oc1 = 0.f;
    {
        const float* vr = g_vc + ((size_t)(b * NC_) * H_ + h) * DH_;
        for (int n = 0; n < nk; n++) {
            float pn = sc[w][n];
            const float* p = vr + (size_t)n * (H_ * DH_);
            oc0 += pn * p[l];
            oc1 += pn * p[l + 32];
        }
    }
    oc0 *= rcs; oc1 *= rcs;

    float fe = 0.f;
    int fkp = 0;
    {
        float fs = -1e30f;
        if (l < 20) {
            const int m = l >> 2, sp = l & 3;
            const int blk2 = (m == 4) ? (s >> 2) : ti[m];
            fkp = blk2 * 4 + sp;
            const bool vis = ((m == 4) || (tv[m] > 0.f)) && (fkp <= s);
            if (vis) {
                const float4* k4 = (const float4*)(g_kr + ((size_t)(b * S_ + fkp) * H_ + h) * DH_);
                fs = dot64(qr4, k4) * 0.125f;
            }
        }
        float fmx = fs;
#pragma unroll
        for (int o = 16; o; o >>= 1) fmx = fmaxf(fmx, __shfl_xor_sync(FULLMASK, fmx, o));
        fe = (fs > -1e29f) ? expf(fs - fmx) : 0.f;
    }
    float fsum = fe;
#pragma unroll
    for (int o = 16; o; o >>= 1) fsum += __shfl_xor_sync(FULLMASK, fsum, o);
    const float rcf = 1.f / fsum;

    float of0 = 0.f, of1 = 0.f;
    for (int j = 0; j < 20; j++) {
        float pj = __shfl_sync(FULLMASK, fe, j);
        int kj   = __shfl_sync(FULLMASK, fkp, j);
        const float* p = g_v + ((size_t)(b * S_ + kj) * H_ + h) * DH_;
        of0 += pj * p[l];
        of1 += pj * p[l + 32];
    }
    of0 *= rcf; of1 *= rcf;

    float se = 0.f;
    {
        const int pos = s - l;
        float ssv = -1e30f;
        if (pos >= 0) {
            const float4* k4 = (const float4*)(g_kr + ((size_t)(b * S_ + pos) * H_ + h) * DH_);
            ssv = dot64(qr4, k4) * 0.125f;
        }
        float smx = ssv;
#pragma unroll
        for (int o = 16; o; o >>= 1) smx = fmaxf(smx, __shfl_xor_sync(FULLMASK, smx, o));
        se = (ssv > -1e29f) ? expf(ssv - smx) : 0.f;
    }
    float ssum = se;
#pragma unroll
    for (int o = 16; o; o >>= 1) ssum += __shfl_xor_sync(FULLMASK, ssum, o);
    const float rcw = 1.f / ssum;

    float os0 = 0.f, os1 = 0.f;
    {
        const int wmax = s < 31 ? s : 31;
        for (int w2 = 0; w2 <= wmax; w2++) {
            float pj = __shfl_sync(FULLMASK, se, w2);
            const float* p = g_v + ((size_t)(b * S_ + (s - w2)) * H_ + h) * DH_;
            os0 += pj * p[l];
            os1 += pj * p[l + 32];
        }
    }
    os0 *= rcw; os1 *= rcw;

    const float* gg = g_gate + (size_t)(b * S_ + s) * 48 + h * 3;
    const float g0 = gg[0], g1 = gg[1], g2 = gg[2];
    float* op = g_o + (size_t)(b * S_ + s) * D_ + h * DH_;
    op[l]      = g0 * oc0 + g1 * of0 + g2 * os0;
    op[l + 32] = g0 * oc1 + g1 * of1 + g2 * os1;
}

// ---------------- launch ----------------
extern "C" void kernel_launch(void* const* d_in, const int* in_sizes, int n_in,
                              void* d_out, int out_size) {
    (void)in_sizes; (void)n_in; (void)out_size;
    const float* x     = (const float*)d_in[0];
    const float* x0    = (const float*)d_in[2];
    const float* lam   = (const float*)d_in[3];
    const float* Wq    = (const float*)d_in[4];
    const float* Wk    = (const float*)d_in[5];
    const float* Wv    = (const float*)d_in[6];
    const float* pos_k = (const float*)d_in[7];
    const float* pos_v = (const float*)d_in[8];
    const float* Wck   = (const float*)d_in[9];
    const float* Wcv   = (const float*)d_in[10];
    const float* mem_k = (const float*)d_in[11];
    const float* mem_v = (const float*)d_in[12];
    const float* Wg    = (const float*)d_in[13];
    const float* Wo    = (const float*)d_in[14];
    const float* Wfc   = (const float*)d_in[15];
    const float* Wproj = (const float*)d_in[16];
    float* out = (float*)d_out;

    cudaFuncSetAttribute(gemm_o_t,    cudaFuncAttributeMaxDynamicSharedMemorySize, SMEM_BYTES);
    cudaFuncSetAttribute(gemm_fc_t,   cudaFuncAttributeMaxDynamicSharedMemorySize, SMEM_BYTES);
    cudaFuncSetAttribute(gemm_proj_t, cudaFuncAttributeMaxDynamicSharedMemorySize, SMEM_BYTES);

    k_trig<<<(S_ * 32) / 256, 256>>>();
    k_rms1<<<ROWS_, 256>>>(x, x0, lam);

    dim3 gqkv(D_ / 128, ROWS_ / 128, 3);   // (8,16,3)
    gemm_qkv<<<gqkv, 256>>>(Wq, Wk, Wv);
    k_gate2<<<ROWS_ / 16, 768>>>(Wg);

    k_compress<<<B_ * NB_ * H_, 64>>>(pos_k, pos_v, Wck, Wcv);
    k_memfill<<<(B_ * H_ * DH_ + 255) / 256, 256>>>(mem_k, mem_v);
    k_rope<<<(B_ * S_ * H_ * 32) / 256, 256>>>();

    k_attn2<<<B_ * H_ * (S_ / 8), 256>>>();

    dim3 g1(D_ / 128, ROWS_ / 128);        // (8,16)
    gemm_o_t<<<g1, 256, SMEM_BYTES>>>(Wo);         // x1 = xr + o@Wo
    k_rms2<<<ROWS_, 256>>>();                      // m = rmsnorm(x1)

    dim3 g2(FD_ / 128, ROWS_ / 128);       // (32,16)
    gemm_fc_t<<<g2, 256, SMEM_BYTES>>>(Wfc);       // act = relu(m@Wfc)^2
    gemm_proj_t<<<g1, 256, SMEM_BYTES>>>(Wproj, out);  // out = x1 + act@Wproj
}

// round 10
// speedup vs baseline: 2.9078x; 1.3271x over previous
#include <cuda_runtime.h>
#include <math.h>

// Problem constants (fixed shapes)
#define B_  2
#define S_  1024
#define D_  1024
#define H_  16
#define DH_ 64
#define NB_ 256
#define NC_ 257     // compressed keys = mem + 256 blocks
#define FD_ 4096
#define ROWS_ (B_*S_)   // 2048
#define FULLMASK 0xffffffffu

// ---------------- scratch (static device arrays; no allocation) ----------------
__device__ float g_xr[B_*S_*D_];
__device__ float g_h [B_*S_*D_];
__device__ float g_q [B_*S_*D_];
__device__ float g_k [B_*S_*D_];
__device__ float g_v [B_*S_*D_];
__device__ float g_qr[B_*S_*D_];
__device__ float g_kr[B_*S_*D_];
__device__ float g_kc[B_*NC_*H_*DH_];
__device__ float g_vc[B_*NC_*H_*DH_];
__device__ float g_gate[B_*S_*48];
__device__ float g_o [B_*S_*D_];
__device__ float g_x1[B_*S_*D_];
__device__ float g_m [B_*S_*D_];
__device__ float g_act[B_*S_*FD_];
__device__ float g_ctab[S_*32];
__device__ float g_stab[S_*32];

// ---------------- K1: xr = l0*x + l1*x0 ; h = rmsnorm(xr) ----------------
__global__ void k_rms1(const float* __restrict__ x, const float* __restrict__ x0,
                       const float* __restrict__ lam) {
    const int row = blockIdx.x;
    const int t = threadIdx.x;
    const float l0 = lam[0], l1 = lam[1];
    const size_t base = (size_t)row * D_;
    __shared__ float red[8];
    __shared__ float s_inv;
    float ss = 0.f;
    for (int i = t; i < D_; i += 256) {
        float v = l0 * x[base + i] + l1 * x0[base + i];
        g_xr[base + i] = v;
        ss += v * v;
    }
#pragma unroll
    for (int o = 16; o; o >>= 1) ss += __shfl_xor_sync(FULLMASK, ss, o);
    if ((t & 31) == 0) red[t >> 5] = ss;
    __syncthreads();
    if (t == 0) {
        float tot = 0.f;
        for (int w = 0; w < 8; w++) tot += red[w];
        s_inv = rsqrtf(tot / (float)D_ + 1e-6f);
    }
    __syncthreads();
    const float inv = s_inv;
    for (int i = t; i < D_; i += 256) g_h[base + i] = g_xr[base + i] * inv;
}

__global__ void k_rms2() {
    const int row = blockIdx.x;
    const int t = threadIdx.x;
    const size_t base = (size_t)row * D_;
    __shared__ float red[8];
    __shared__ float s_inv;
    float ss = 0.f;
    for (int i = t; i < D_; i += 256) { float v = g_x1[base + i]; ss += v * v; }
#pragma unroll
    for (int o = 16; o; o >>= 1) ss += __shfl_xor_sync(FULLMASK, ss, o);
    if ((t & 31) == 0) red[t >> 5] = ss;
    __syncthreads();
    if (t == 0) {
        float tot = 0.f;
        for (int w = 0; w < 8; w++) tot += red[w];
        s_inv = rsqrtf(tot / (float)D_ + 1e-6f);
    }
    __syncthreads();
    const float inv = s_inv;
    for (int i = t; i < D_; i += 256) g_m[base + i] = g_x1[base + i] * inv;
}

// ================= 3xTF32 tensor-core GEMM (error-compensated, mma.sync m16n8k8) =================
// CTA tile 128x128, BK=32, 8 warps (2x4), warp tile 64x32, cp.async double buffer.
#define ASZ 4608    // 128*36
#define BSZ 4352    // 32*136
#define BUFSZ 8960  // ASZ+BSZ
#define SMEM_BYTES (2*BUFSZ*4)   // 71680

__device__ __forceinline__ void cp16(void* dst_smem, const void* src) {
    unsigned d = (unsigned)__cvta_generic_to_shared(dst_smem);
    asm volatile("cp.async.ca.shared.global [%0], [%1], 16;" :: "r"(d), "l"(src));
}

__device__ __forceinline__ unsigned tf32_rna(float x) {
    unsigned r;
    asm("cvt.rna.tf32.f32 %0, %1;" : "=r"(r) : "f"(x));
    return r;
}
__device__ __forceinline__ void split_tf32(float x, unsigned &hi, unsigned &lo) {
    hi = tf32_rna(x);
    lo = tf32_rna(x - __uint_as_float(hi));
}

__device__ __forceinline__ void mma_tf32(float c[4], const unsigned a[4], const unsigned b[2]) {
    asm volatile(
        "mma.sync.aligned.m16n8k8.row.col.f32.tf32.tf32.f32 "
        "{%0,%1,%2,%3}, {%4,%5,%6,%7}, {%8,%9}, {%0,%1,%2,%3};"
        : "+f"(c[0]), "+f"(c[1]), "+f"(c[2]), "+f"(c[3])
        : "r"(a[0]), "r"(a[1]), "r"(a[2]), "r"(a[3]), "r"(b[0]), "r"(b[1]));
}

// EPI: 0 = plain store, 1 = +Add, 2 = relu^2
template <int EPI>
__device__ __forceinline__ void mma_gemm(const float* __restrict__ A,
                                         const float* __restrict__ Bm,
                                         float* __restrict__ C,
                                         const float* __restrict__ Add,
                                         int N, int K) {
    extern __shared__ float smem[];
    const int tid = threadIdx.x;
    const int warp = tid >> 5, lane = tid & 31;
    const int wm = warp >> 2, wn = warp & 3;
    const int g = lane >> 2, tg = lane & 3;
    const int tileM = blockIdx.y * 128, tileN = blockIdx.x * 128;

    float acc[4][4][4];
#pragma unroll
    for (int mt = 0; mt < 4; mt++)
#pragma unroll
        for (int nt = 0; nt < 4; nt++)
#pragma unroll
            for (int c = 0; c < 4; c++) acc[mt][nt][c] = 0.f;

    const int ar = tid >> 3, ac0 = (tid & 7) << 2;
    const int bk = tid >> 5, bn0 = (tid & 31) << 2;

    const int niter = K >> 5;

    {
        float* Ab = smem;
        float* Bb = smem + ASZ;
#pragma unroll
        for (int p = 0; p < 4; p++) {
            int r = ar + p * 32;
            cp16(Ab + r * 36 + ac0, A + (size_t)(tileM + r) * K + ac0);
        }
#pragma unroll
        for (int p = 0; p < 4; p++) {
            int kk = bk + p * 8;
            cp16(Bb + kk * 136 + bn0, Bm + (size_t)kk * N + tileN + bn0);
        }
        asm volatile("cp.async.commit_group;" ::: "memory");
    }

    for (int i = 0; i < niter; i++) {
        if (i + 1 < niter) {
            const int k0 = (i + 1) << 5;
            float* Ab = smem + ((i + 1) & 1) * BUFSZ;
            float* Bb = Ab + ASZ;
#pragma unroll
            for (int p = 0; p < 4; p++) {
                int r = ar + p * 32;
                cp16(Ab + r * 36 + ac0, A + (size_t)(tileM + r) * K + k0 + ac0);
            }
#pragma unroll
            for (int p = 0; p < 4; p++) {
                int kk = bk + p * 8;
                cp16(Bb + kk * 136 + bn0, Bm + (size_t)(k0 + kk) * N + tileN + bn0);
            }
            asm volatile("cp.async.commit_group;" ::: "memory");
            asm volatile("cp.async.wait_group 1;" ::: "memory");
        } else {
            asm volatile("cp.async.wait_group 0;" ::: "memory");
        }
        __syncthreads();

        const float* Ab = smem + (i & 1) * BUFSZ;
        const float* Bb = Ab + ASZ;
#pragma unroll
        for (int kt = 0; kt < 4; kt++) {
            unsigned afh[4][4], afl[4][4], bfh[4][2], bfl[4][2];
#pragma unroll
            for (int mt = 0; mt < 4; mt++) {
                const float* ap = Ab + (wm * 64 + mt * 16 + g) * 36 + kt * 8 + tg;
                split_tf32(ap[0],          afh[mt][0], afl[mt][0]);
                split_tf32(ap[8 * 36],     afh[mt][1], afl[mt][1]);
                split_tf32(ap[4],          afh[mt][2], afl[mt][2]);
                split_tf32(ap[8 * 36 + 4], afh[mt][3], afl[mt][3]);
            }
#pragma unroll
            for (int nt = 0; nt < 4; nt++) {
                const float* bp = Bb + (kt * 8 + tg) * 136 + wn * 32 + nt * 8 + g;
                split_tf32(bp[0],       bfh[nt][0], bfl[nt][0]);
                split_tf32(bp[4 * 136], bfh[nt][1], bfl[nt][1]);
            }
#pragma unroll
            for (int mt = 0; mt < 4; mt++)
#pragma unroll
                for (int nt = 0; nt < 4; nt++) {
                    mma_tf32(acc[mt][nt], afh[mt], bfl[nt]);  // hi*lo
                    mma_tf32(acc[mt][nt], afl[mt], bfh[nt]);  // lo*hi
                    mma_tf32(acc[mt][nt], afh[mt], bfh[nt]);  // hi*hi
                }
        }
        __syncthreads();
    }

#pragma unroll
    for (int mt = 0; mt < 4; mt++) {
#pragma unroll
        for (int nt = 0; nt < 4; nt++) {
            const int row = tileM + wm * 64 + mt * 16 + g;
            const int col = tileN + wn * 32 + nt * 8 + tg * 2;
            float2 v0 = make_float2(acc[mt][nt][0], acc[mt][nt][1]);
            float2 v1 = make_float2(acc[mt][nt][2], acc[mt][nt][3]);
            size_t i0 = (size_t)row * N + col;
            size_t i1 = (size_t)(row + 8) * N + col;
            if (EPI == 1) {
                float2 a0 = *(const float2*)(Add + i0);
                float2 a1 = *(const float2*)(Add + i1);
                v0.x += a0.x; v0.y += a0.y;
                v1.x += a1.x; v1.y += a1.y;
            } else if (EPI == 2) {
                v0.x = fmaxf(v0.x, 0.f); v0.x *= v0.x;
                v0.y = fmaxf(v0.y, 0.f); v0.y *= v0.y;
                v1.x = fmaxf(v1.x, 0.f); v1.x *= v1.x;
                v1.y = fmaxf(v1.y, 0.f); v1.y *= v1.y;
            }
            *(float2*)(C + i0) = v0;
            *(float2*)(C + i1) = v1;
        }
    }
}

__global__ void __launch_bounds__(256) gemm_qkv_t(const float* __restrict__ Wq,
                                                  const float* __restrict__ Wk,
                                                  const float* __restrict__ Wv) {
    const int z = blockIdx.z;
    const float* W = (z == 0) ? Wq : (z == 1) ? Wk : Wv;
    float* Cp = (z == 0) ? g_q : (z == 1) ? g_k : g_v;
    mma_gemm<0>(g_h, W, Cp, nullptr, D_, D_);
}
__global__ void __launch_bounds__(256) gemm_o_t(const float* __restrict__ W) {
    mma_gemm<1>(g_o, W, g_x1, g_xr, D_, D_);
}
__global__ void __launch_bounds__(256) gemm_fc_t(const float* __restrict__ W) {
    mma_gemm<2>(g_m, W, g_act, nullptr, FD_, D_);
}
__global__ void __launch_bounds__(256) gemm_proj_t(const float* __restrict__ W, float* __restrict__ out) {
    mma_gemm<1>(g_act, W, out, g_x1, D_, FD_);
}

// ---------------- gates: tiled, 16 rows x 48 cols per block ----------------
__global__ void __launch_bounds__(768) k_gate2(const float* __restrict__ Wg) {
    __shared__ float sh[16 * 128];
    __shared__ float sw[128 * 48];
    const int t = threadIdx.x;
    const int r = t / 48, c = t % 48;
    const int row0 = blockIdx.x * 16;
    float acc = 0.f;
    for (int k0 = 0; k0 < D_; k0 += 128) {
        for (int i = t; i < 16 * 128; i += 768)
            sh[i] = g_h[(size_t)(row0 + (i >> 7)) * D_ + k0 + (i & 127)];
        for (int i = t; i < 128 * 48; i += 768)
            sw[i] = Wg[(size_t)(k0 + i / 48) * 48 + (i % 48)];
        __syncthreads();
        const float* hr = &sh[r * 128];
#pragma unroll 8
        for (int kk = 0; kk < 128; kk++) acc += hr[kk] * sw[kk * 48 + c];
        __syncthreads();
    }
    g_gate[(size_t)(row0 + r) * 48 + c] = 1.f / (1.f + expf(-acc));
}

// ---------------- block compression: kc/vc for n>=1 ----------------
__global__ void k_compress(const float* __restrict__ pos_k, const float* __restrict__ pos_v,
                           const float* __restrict__ Wck, const float* __restrict__ Wcv) {
    const int idx = blockIdx.x;   // B*NB*H = 8192
    const int h = idx & (H_ - 1);
    const int n = (idx >> 4) & (NB_ - 1);
    const int b = idx >> 12;
    const int t = threadIdx.x;    // 64
    __shared__ float kb[256], vb[256];
    for (int r = t; r < 256; r += 64) {
        const int sp = r >> 6, d = r & 63;
        const int s = n * 4 + sp;
        const size_t src = ((size_t)(b * S_ + s) * H_ + h) * DH_ + d;
        kb[r] = g_k[src] + pos_k[(h * 4 + sp) * DH_ + d];
        vb[r] = g_v[src] + pos_v[(h * 4 + sp) * DH_ + d];
    }
    __syncthreads();
    float ak = 0.f, av = 0.f;
    for (int r = 0; r < 256; r++) {
        ak += kb[r] * Wck[r * DH_ + t];
        av += vb[r] * Wcv[r * DH_ + t];
    }
    const size_t dst = ((size_t)(b * NC_ + (n + 1)) * H_ + h) * DH_ + t;
    g_kc[dst] = ak;
    g_vc[dst] = av;
}

__global__ void k_memfill(const float* __restrict__ mem_k, const float* __restrict__ mem_v) {
    const int i = blockIdx.x * blockDim.x + threadIdx.x;  // B*H*DH = 2048
    if (i >= B_ * H_ * DH_) return;
    const int d = i & 63, h = (i >> 6) & (H_ - 1), b = i >> 10;
    const size_t dst = ((size_t)(b * NC_ + 0) * H_ + h) * DH_ + d;
    g_kc[dst] = mem_k[h * DH_ + d];
    g_vc[dst] = mem_v[h * DH_ + d];
}

// ---------------- trig table + RoPE ----------------
__global__ void k_trig() {
    const int i = blockIdx.x * blockDim.x + threadIdx.x;  // S*32
    if (i >= S_ * 32) return;
    const int p = i & 31;
    const int s = i >> 5;
    const float inv = exp2f(-(float)p * (13.287712379549449f / 32.f));
    const float tt = (float)s * inv;
    g_ctab[i] = cosf(tt);
    g_stab[i] = sinf(tt);
}

__global__ void k_rope() {
    const int i = blockIdx.x * blockDim.x + threadIdx.x;  // B*S*H*32
    if (i >= B_ * S_ * H_ * 32) return;
    const int p = i & 31;
    const int h = (i >> 5) & (H_ - 1);
    const int s = (i >> 9) & (S_ - 1);
    const int b = i >> 19;
    const float c  = g_ctab[s * 32 + p];
    const float sn = g_stab[s * 32 + p];
    const size_t base = ((size_t)(b * S_ + s) * H_ + h) * DH_;
    float q1 = g_q[base + p], q2 = g_q[base + 32 + p];
    g_qr[base + p]      = q1 * c - q2 * sn;
    g_qr[base + 32 + p] = q1 * sn + q2 * c;
    float k1 = g_k[base + p], k2 = g_k[base + 32 + p];
    g_kr[base + p]      = k1 * c - k2 * sn;
    g_kr[base + 32 + p] = k1 * sn + k2 * c;
}

// ---------------- attention v3: smem-tiled compressed + sliding, warp-per-query ----------------
// Block = 8 queries (one (b,h), s0..s0+7), 256 threads. Key tiles staged in smem
// with pitch 65 (bank-conflict-free: bank = (row + d) % 32).
#define KTP 65     // tile row pitch (floats)

__global__ void __launch_bounds__(256) k_attn3() {
    const int blk = blockIdx.x;            // B*H*(S/8) = 4096
    const int s0 = (blk & 127) << 3;
    const int h = (blk >> 7) & (H_ - 1);
    const int b = blk >> 11;
    const int w = threadIdx.x >> 5;        // warp = query within tile
    const int l = threadIdx.x & 31;
    const int s = s0 + w;
    const int tid = threadIdx.x;

    __shared__ float qs[8][64];
    __shared__ float qrs[8][64];
    __shared__ float sc[8][260];
    __shared__ float buf[5200];            // 64*65=4160 (kc/vc tile) or 2*40*65=5200 (slide)

    const size_t qbase = ((size_t)(b * S_ + s) * H_ + h) * DH_;
    qs [w][l]      = g_q [qbase + l];
    qs [w][l + 32] = g_q [qbase + 32 + l];
    qrs[w][l]      = g_qr[qbase + l];
    qrs[w][l + 32] = g_qr[qbase + 32 + l];
    __syncwarp();

    const int nvisB = (s >= 3) ? (((s - 3) >> 2) + 1) : 0;
    const int nk = nvisB + 1;
    // block-wide key count (query s0+7 has the most)
    const int nkb = (((s0 + 7) >= 3) ? (((s0 + 4) >> 2) + 1) : 0) + 1;

    const float* kcbase = g_kc + ((size_t)b * NC_ * H_ + h) * DH_;   // + n*H_*DH_
    const float* vcbase = g_vc + ((size_t)b * NC_ * H_ + h) * DH_;
    const float* qsw  = qs[w];
    const float* qrsw = qrs[w];

    // ===== Phase A: compressed scores (tiled kc) =====
    float mymax = -1e30f;
    for (int n0 = 0; n0 < nkb; n0 += 64) {
        __syncthreads();
        // stage 64 kc rows, coalesced
#pragma unroll
        for (int i = 0; i < 16; i++) {
            const int e = tid + 256 * i;          // 0..4095
            const int r = e >> 6, c = e & 63;
            int n = n0 + r; if (n > NC_ - 1) n = NC_ - 1;
            buf[r * KTP + c] = kcbase[(size_t)n * (H_ * DH_) + c];
        }
        __syncthreads();
#pragma unroll
        for (int sub = 0; sub < 2; sub++) {
            const int n = n0 + sub * 32 + l;
            if (n < nk) {
                const float* kr_ = &buf[(sub * 32 + l) * KTP];
                float a = 0.f;
#pragma unroll
                for (int d = 0; d < 64; d++) a += qsw[d] * kr_[d];
                a *= 0.125f;
                sc[w][n] = a;
                mymax = fmaxf(mymax, a);
            }
        }
    }
#pragma unroll
    for (int o = 16; o; o >>= 1) mymax = fmaxf(mymax, __shfl_xor_sync(FULLMASK, mymax, o));

    // exp + sum (lane-strided, ascending n per lane — same order as before)
    float mysum = 0.f;
    for (int n = l; n < nk; n += 32) {
        float e = expf(sc[w][n] - mymax);
        sc[w][n] = e;
        mysum += e;
    }
#pragma unroll
    for (int o = 16; o; o >>= 1) mysum += __shfl_xor_sync(FULLMASK, mysum, o);
    const float rcs = 1.f / mysum;

    // ===== top-4 blocks (exclude n==0); ties -> lower index =====
    float tv[4] = {-1.f, -1.f, -1.f, -1.f};
    int   ti[4] = {0, 0, 0, 0};
    for (int n = l; n < nk; n += 32) {
        if (n >= 1) {
            float vI = sc[w][n];
            if (vI > tv[3]) {
                int p2 = 3;
                while (p2 > 0 && vI > tv[p2 - 1]) {
                    tv[p2] = tv[p2 - 1]; ti[p2] = ti[p2 - 1]; p2--;
                }
                tv[p2] = vI; ti[p2] = n - 1;
            }
        }
    }
#pragma unroll
    for (int off = 16; off; off >>= 1) {
        float ov[4]; int oi[4];
#pragma unroll
        for (int m = 0; m < 4; m++) {
            ov[m] = __shfl_xor_sync(FULLMASK, tv[m], off);
            oi[m] = __shfl_xor_sync(FULLMASK, ti[m], off);
        }
#pragma unroll
        for (int m = 0; m < 4; m++) {
            float v2 = ov[m]; int i2 = oi[m];
            if ((v2 > tv[3]) || (v2 == tv[3] && i2 < ti[3])) {
                int p2 = 3;
                while (p2 > 0 && ((v2 > tv[p2 - 1]) || (v2 == tv[p2 - 1] && i2 < ti[p2 - 1]))) {
                    tv[p2] = tv[p2 - 1]; ti[p2] = ti[p2 - 1]; p2--;
                }
                tv[p2] = v2; ti[p2] = i2;
            }
        }
    }

    // ===== Phase B: compressed PV (tiled vc); lane owns dims l, l+32 =====
    float oc0 = 0.f, oc1 = 0.f;
    for (int n0 = 0; n0 < nkb; n0 += 64) {
        __syncthreads();
#pragma unroll
        for (int i = 0; i < 16; i++) {
            const int e = tid + 256 * i;
            const int r = e >> 6, c = e & 63;
            int n = n0 + r; if (n > NC_ - 1) n = NC_ - 1;
            buf[r * KTP + c] = vcbase[(size_t)n * (H_ * DH_) + c];
        }
        __syncthreads();
        const int jmax = (nk - n0 < 64) ? (nk - n0) : 64;
        for (int j = 0; j < jmax; j++) {
            const float pn = sc[w][n0 + j];
            oc0 += pn * buf[j * KTP + l];
            oc1 += pn * buf[j * KTP + l + 32];
        }
    }
    oc0 *= rcs; oc1 *= rcs;

    // ===== Phase C: fine (20 gathered keys) =====
    float fe = 0.f;
    int fkp = 0;
    {
        float fs = -1e30f;
        if (l < 20) {
            const int m = l >> 2, sp = l & 3;
            const int blk2 = (m == 4) ? (s >> 2) : ti[m];
            fkp = blk2 * 4 + sp;
            const bool vis = ((m == 4) || (tv[m] > 0.f)) && (fkp <= s);
            if (vis) {
                const float* kp = g_kr + ((size_t)(b * S_ + fkp) * H_ + h) * DH_;
                fs = 0.f;
#pragma unroll
                for (int d = 0; d < 64; d += 4) {
                    float4 x = *(const float4*)(qrsw + d);
                    float4 y = *(const float4*)(kp + d);
                    fs += x.x * y.x + x.y * y.y + x.z * y.z + x.w * y.w;
                }
                fs *= 0.125f;
            }
        }
        float fmx = fs;
#pragma unroll
        for (int o = 16; o; o >>= 1) fmx = fmaxf(fmx, __shfl_xor_sync(FULLMASK, fmx, o));
        fe = (fs > -1e29f) ? expf(fs - fmx) : 0.f;
    }
    float fsum = fe;
#pragma unroll
    for (int o = 16; o; o >>= 1) fsum += __shfl_xor_sync(FULLMASK, fsum, o);
    const float rcf = 1.f / fsum;

    float of0 = 0.f, of1 = 0.f;
    for (int j = 0; j < 20; j++) {
        float pj = __shfl_sync(FULLMASK, fe, j);
        int kj   = __shfl_sync(FULLMASK, fkp, j);
        const float* p = g_v + ((size_t)(b * S_ + kj) * H_ + h) * DH_;
        of0 += pj * p[l];
        of1 += pj * p[l + 32];
    }
    of0 *= rcf; of1 *= rcf;

    // ===== Phase D: sliding window 32 (staged rows s0-31 .. s0+7) =====
    __syncthreads();
    {
        const int base = s0 - 31;
        // stage 40 rows of kr into buf[0..2599], 40 rows of v into buf[2600..5199]
#pragma unroll
        for (int i = 0; i < 10; i++) {
            const int e = tid + 256 * i;          // 0..2559
            const int r = e >> 6, c = e & 63;
            int rs = base + r; if (rs < 0) rs = 0;
            const size_t src = ((size_t)(b * S_ + rs) * H_ + h) * DH_ + c;
            buf[r * KTP + c]        = g_kr[src];
            buf[2600 + r * KTP + c] = g_v [src];
        }
    }
    __syncthreads();

    float se = 0.f;
    {
        const int pos = s - l;
        float ssv = -1e30f;
        if (pos >= 0) {
            const float* kr_ = &buf[(w + 31 - l) * KTP];
            ssv = 0.f;
#pragma unroll
            for (int d = 0; d < 64; d++) ssv += qrsw[d] * kr_[d];
            ssv *= 0.125f;
        }
        float smx = ssv;
#pragma unroll
        for (int o = 16; o; o >>= 1) smx = fmaxf(smx, __shfl_xor_sync(FULLMASK, smx, o));
        se = (ssv > -1e29f) ? expf(ssv - smx) : 0.f;
    }
    float ssum = se;
#pragma unroll
    for (int o = 16; o; o >>= 1) ssum += __shfl_xor_sync(FULLMASK, ssum, o);
    const float rcw = 1.f / ssum;

    float os0 = 0.f, os1 = 0.f;
    {
        const int wmax = s < 31 ? s : 31;
        for (int w2 = 0; w2 <= wmax; w2++) {
            float pj = __shfl_sync(FULLMASK, se, w2);
            const float* vr = &buf[2600 + (w + 31 - w2) * KTP];
            os0 += pj * vr[l];
            os1 += pj * vr[l + 32];
        }
    }
    os0 *= rcw; os1 *= rcw;

    // ===== gate + write =====
    const float* gg = g_gate + (size_t)(b * S_ + s) * 48 + h * 3;
    const float g0 = gg[0], g1 = gg[1], g2 = gg[2];
    float* op = g_o + (size_t)(b * S_ + s) * D_ + h * DH_;
    op[l]      = g0 * oc0 + g1 * of0 + g2 * os0;
    op[l + 32] = g0 * oc1 + g1 * of1 + g2 * os1;
}

// ---------------- launch ----------------
extern "C" void kernel_launch(void* const* d_in, const int* in_sizes, int n_in,
                              void* d_out, int out_size) {
    (void)in_sizes; (void)n_in; (void)out_size;
    const float* x     = (const float*)d_in[0];
    const float* x0    = (const float*)d_in[2];
    const float* lam   = (const float*)d_in[3];
    const float* Wq    = (const float*)d_in[4];
    const float* Wk    = (const float*)d_in[5];
    const float* Wv    = (const float*)d_in[6];
    const float* pos_k = (const float*)d_in[7];
    const float* pos_v = (const float*)d_in[8];
    const float* Wck   = (const float*)d_in[9];
    const float* Wcv   = (const float*)d_in[10];
    const float* mem_k = (const float*)d_in[11];
    const float* mem_v = (const float*)d_in[12];
    const float* Wg    = (const float*)d_in[13];
    const float* Wo    = (const float*)d_in[14];
    const float* Wfc   = (const float*)d_in[15];
    const float* Wproj = (const float*)d_in[16];
    float* out = (float*)d_out;

    cudaFuncSetAttribute(gemm_qkv_t,  cudaFuncAttributeMaxDynamicSharedMemorySize, SMEM_BYTES);
    cudaFuncSetAttribute(gemm_o_t,    cudaFuncAttributeMaxDynamicSharedMemorySize, SMEM_BYTES);
    cudaFuncSetAttribute(gemm_fc_t,   cudaFuncAttributeMaxDynamicSharedMemorySize, SMEM_BYTES);
    cudaFuncSetAttribute(gemm_proj_t, cudaFuncAttributeMaxDynamicSharedMemorySize, SMEM_BYTES);

    k_trig<<<(S_ * 32) / 256, 256>>>();
    k_rms1<<<ROWS_, 256>>>(x, x0, lam);

    dim3 gqkv(D_ / 128, ROWS_ / 128, 3);   // (8,16,3)
    gemm_qkv_t<<<gqkv, 256, SMEM_BYTES>>>(Wq, Wk, Wv);
    k_gate2<<<ROWS_ / 16, 768>>>(Wg);

    k_compress<<<B_ * NB_ * H_, 64>>>(pos_k, pos_v, Wck, Wcv);
    k_memfill<<<(B_ * H_ * DH_ + 255) / 256, 256>>>(mem_k, mem_v);
    k_rope<<<(B_ * S_ * H_ * 32) / 256, 256>>>();

    k_attn3<<<B_ * H_ * (S_ / 8), 256>>>();

    dim3 g1(D_ / 128, ROWS_ / 128);        // (8,16)
    gemm_o_t<<<g1, 256, SMEM_BYTES>>>(Wo);         // x1 = xr + o@Wo
    k_rms2<<<ROWS_, 256>>>();                      // m = rmsnorm(x1)

    dim3 g2(FD_ / 128, ROWS_ / 128);       // (32,16)
    gemm_fc_t<<<g2, 256, SMEM_BYTES>>>(Wfc);       // act = relu(m@Wfc)^2
    gemm_proj_t<<<g1, 256, SMEM_BYTES>>>(Wproj, out);  // out = x1 + act@Wproj
}